// round 1
// baseline (speedup 1.0000x reference)
#include <cuda_runtime.h>
#include <cuda_bf16.h>

// Problem constants
#define NN_ 8192          // nodes
#define EE_ 524288        // edges
#define HH_ 128           // hidden
#define IND_ 32           // in_dim
#define NCC_ 16           // classes

// Device scratch (static, no allocations)
__device__ float g_cx[NN_ * HH_];    // coded_x
__device__ float g_agg[NN_ * HH_];   // segment-sum accumulator
__device__ float g_z[NN_ * HH_];     // z
__device__ int   g_is64;             // edge_index dtype flag

// ---------------------------------------------------------------------------
// vectorized global reduction (sm_90+)
__device__ __forceinline__ void red_add_v4(float* addr, float x, float y, float z, float w) {
    asm volatile("red.global.add.v4.f32 [%0], {%1,%2,%3,%4};"
                 :: "l"(addr), "f"(x), "f"(y), "f"(z), "f"(w) : "memory");
}

// ---------------------------------------------------------------------------
// K0: detect int64 vs int32 edge_index layout.
// int64 little-endian -> odd 32-bit words are all 0 (indices in [0, 8192)).
__global__ void k_detect(const int* __restrict__ ei32) {
    if (threadIdx.x == 0) {
        int all0 = 1;
        for (int i = 0; i < 64; ++i) {
            if (ei32[2 * i + 1] != 0) { all0 = 0; break; }
        }
        g_is64 = all0;
    }
}

// K0b: zero the aggregation buffer
__global__ void k_zero_agg() {
    int idx = blockIdx.x * blockDim.x + threadIdx.x;
    float4* p = reinterpret_cast<float4*>(g_agg);
    int n4 = NN_ * HH_ / 4;
    for (int i = idx; i < n4; i += gridDim.x * blockDim.x)
        p[i] = make_float4(0.f, 0.f, 0.f, 0.f);
}

// ---------------------------------------------------------------------------
// K1: node encoder. coded_x = (prelu(x@W1+b1)) @ W2 + b2
// grid = 64 blocks of 128 nodes, 256 threads, 8x8 microtiles.
__global__ void __launch_bounds__(256, 2)
k_node_enc(const float* __restrict__ x,
           const float* __restrict__ W1, const float* __restrict__ b1,
           const float* __restrict__ a_p,
           const float* __restrict__ W2, const float* __restrict__ b2)
{
    extern __shared__ float sm[];
    float* shA = sm;                 // [128][129] hidden h
    float* shB = shA + 128 * 129;    // [32][128] weight chunk
    float* shX = shB + 32 * 128;     // [128][33] x tile
    int tid = threadIdx.x;
    int tx = tid & 15, ty = tid >> 4;
    int base = blockIdx.x * 128;

    for (int idx = tid; idx < 128 * IND_; idx += 256) {
        int r = idx >> 5, k = idx & 31;
        shX[r * 33 + k] = x[(base + r) * IND_ + k];
    }
    for (int idx = tid; idx < IND_ * 128; idx += 256) shB[idx] = W1[idx];
    __syncthreads();

    float acc[8][8];
#pragma unroll
    for (int i = 0; i < 8; ++i)
#pragma unroll
        for (int j = 0; j < 8; ++j) acc[i][j] = 0.f;

#pragma unroll 4
    for (int k = 0; k < IND_; ++k) {
        float af[8];
#pragma unroll
        for (int i = 0; i < 8; ++i) af[i] = shX[(ty * 8 + i) * 33 + k];
        float4 b0 = *(const float4*)&shB[k * 128 + tx * 8];
        float4 b1v = *(const float4*)&shB[k * 128 + tx * 8 + 4];
        float bfr[8] = {b0.x, b0.y, b0.z, b0.w, b1v.x, b1v.y, b1v.z, b1v.w};
#pragma unroll
        for (int i = 0; i < 8; ++i)
#pragma unroll
            for (int j = 0; j < 8; ++j) acc[i][j] = fmaf(af[i], bfr[j], acc[i][j]);
    }

    float a = *a_p;
    // prelu + store hidden to shA
#pragma unroll
    for (int i = 0; i < 8; ++i)
#pragma unroll
        for (int j = 0; j < 8; ++j) {
            float v = acc[i][j] + b1[tx * 8 + j];
            v = (v >= 0.f) ? v : a * v;
            shA[(ty * 8 + i) * 129 + tx * 8 + j] = v;
            acc[i][j] = 0.f;
        }

    for (int kc = 0; kc < HH_; kc += 32) {
        __syncthreads();
        for (int idx = tid; idx < 32 * 128; idx += 256) shB[idx] = W2[kc * 128 + idx];
        __syncthreads();
#pragma unroll 4
        for (int k = 0; k < 32; ++k) {
            float af[8];
#pragma unroll
            for (int i = 0; i < 8; ++i) af[i] = shA[(ty * 8 + i) * 129 + kc + k];
            float4 b0 = *(const float4*)&shB[k * 128 + tx * 8];
            float4 b1v = *(const float4*)&shB[k * 128 + tx * 8 + 4];
            float bfr[8] = {b0.x, b0.y, b0.z, b0.w, b1v.x, b1v.y, b1v.z, b1v.w};
#pragma unroll
            for (int i = 0; i < 8; ++i)
#pragma unroll
                for (int j = 0; j < 8; ++j) acc[i][j] = fmaf(af[i], bfr[j], acc[i][j]);
        }
    }
#pragma unroll
    for (int i = 0; i < 8; ++i) {
        int row = base + ty * 8 + i;
#pragma unroll
        for (int j = 0; j < 8; ++j)
            g_cx[row * HH_ + tx * 8 + j] = acc[i][j] + b2[tx * 8 + j];
    }
}

// ---------------------------------------------------------------------------
// K2: fused edge pipeline.
// h1 = prelu(edge_attr @ eeW1 + b1); ce = h1 @ eeW2 + b2;
// msg = relu(coded_x[src] + ce); red.add into agg[dst].
// grid = E/128 = 4096 blocks, 256 threads.
__global__ void __launch_bounds__(256, 2)
k_edge(const float* __restrict__ ea, const int* __restrict__ ei32,
       const float* __restrict__ W1, const float* __restrict__ b1,
       const float* __restrict__ a_p,
       const float* __restrict__ W2, const float* __restrict__ b2)
{
    extern __shared__ float sm[];
    float* shH = sm;                  // [128][129] h1
    float* shB = shH + 128 * 129;     // [32][128] W2 chunk
    float* shEA = shB + 32 * 128;     // [128][4]
    float* shW1 = shEA + 512;         // [4][128]
    int* shSrc = (int*)(shW1 + 512);  // [128]
    int* shDst = shSrc + 128;

    int tid = threadIdx.x;
    int tx = tid & 15, ty = tid >> 4;
    int e0 = blockIdx.x * 128;
    int is64 = g_is64;

    if (tid < 128) {
        int e = tid;
        if (is64) {
            shSrc[e] = ei32[2 * (e0 + e)];
            shDst[e] = ei32[2 * (EE_ + e0 + e)];
        } else {
            shSrc[e] = ei32[e0 + e];
            shDst[e] = ei32[EE_ + e0 + e];
        }
    }
    for (int idx = tid; idx < 512; idx += 256) {
        shEA[idx] = ea[e0 * 4 + idx];
        shW1[idx] = W1[idx];
    }
    __syncthreads();

    float a = *a_p;
    for (int idx = tid; idx < 128 * 128; idx += 256) {
        int e = idx >> 7, j = idx & 127;
        float v = b1[j];
#pragma unroll
        for (int k = 0; k < 4; ++k) v += shEA[e * 4 + k] * shW1[k * 128 + j];
        shH[e * 129 + j] = (v >= 0.f) ? v : a * v;
    }

    float acc[8][8];
#pragma unroll
    for (int i = 0; i < 8; ++i)
#pragma unroll
        for (int j = 0; j < 8; ++j) acc[i][j] = 0.f;

    for (int kc = 0; kc < HH_; kc += 32) {
        __syncthreads();
        for (int idx = tid; idx < 32 * 128; idx += 256) shB[idx] = W2[kc * 128 + idx];
        __syncthreads();
#pragma unroll 4
        for (int k = 0; k < 32; ++k) {
            float af[8];
#pragma unroll
            for (int i = 0; i < 8; ++i) af[i] = shH[(ty * 8 + i) * 129 + kc + k];
            float4 b0 = *(const float4*)&shB[k * 128 + tx * 8];
            float4 b1v = *(const float4*)&shB[k * 128 + tx * 8 + 4];
            float bfr[8] = {b0.x, b0.y, b0.z, b0.w, b1v.x, b1v.y, b1v.z, b1v.w};
#pragma unroll
            for (int i = 0; i < 8; ++i)
#pragma unroll
                for (int j = 0; j < 8; ++j) acc[i][j] = fmaf(af[i], bfr[j], acc[i][j]);
        }
    }

    float bv[8];
#pragma unroll
    for (int j = 0; j < 8; ++j) bv[j] = b2[tx * 8 + j];

#pragma unroll
    for (int i = 0; i < 8; ++i) {
        int r = ty * 8 + i;
        int s = shSrc[r], d = shDst[r];
        const float4 cx0 = *(const float4*)&g_cx[s * HH_ + tx * 8];
        const float4 cx1 = *(const float4*)&g_cx[s * HH_ + tx * 8 + 4];
        float m0 = fmaxf(0.f, acc[i][0] + bv[0] + cx0.x);
        float m1 = fmaxf(0.f, acc[i][1] + bv[1] + cx0.y);
        float m2 = fmaxf(0.f, acc[i][2] + bv[2] + cx0.z);
        float m3 = fmaxf(0.f, acc[i][3] + bv[3] + cx0.w);
        float m4 = fmaxf(0.f, acc[i][4] + bv[4] + cx1.x);
        float m5 = fmaxf(0.f, acc[i][5] + bv[5] + cx1.y);
        float m6 = fmaxf(0.f, acc[i][6] + bv[6] + cx1.z);
        float m7 = fmaxf(0.f, acc[i][7] + bv[7] + cx1.w);
        red_add_v4(&g_agg[d * HH_ + tx * 8], m0, m1, m2, m3);
        red_add_v4(&g_agg[d * HH_ + tx * 8 + 4], m4, m5, m6, m7);
    }
}

// ---------------------------------------------------------------------------
// K3: GINE mlp (single iteration — loop invariant).
// t = (1+eps)*coded_x + agg; h = prelu(t@gW1+b1); z = h@gW2+b2
__global__ void __launch_bounds__(256, 2)
k_mlp(const float* __restrict__ W1, const float* __restrict__ b1,
      const float* __restrict__ a_p,
      const float* __restrict__ W2, const float* __restrict__ b2,
      const float* __restrict__ eps_p, float* __restrict__ out_z)
{
    extern __shared__ float sm[];
    float* shA = sm;               // [128][129]
    float* shB = shA + 128 * 129;  // [32][128]
    int tid = threadIdx.x;
    int tx = tid & 15, ty = tid >> 4;
    int base = blockIdx.x * 128;

    float ep = 1.0f + *eps_p;
    for (int idx = tid; idx < 128 * 128; idx += 256) {
        int r = idx >> 7, k = idx & 127;
        int g = (base + r) * HH_ + k;
        shA[r * 129 + k] = ep * g_cx[g] + g_agg[g];
    }

    float acc[8][8];
#pragma unroll
    for (int i = 0; i < 8; ++i)
#pragma unroll
        for (int j = 0; j < 8; ++j) acc[i][j] = 0.f;

    for (int kc = 0; kc < HH_; kc += 32) {
        __syncthreads();
        for (int idx = tid; idx < 32 * 128; idx += 256) shB[idx] = W1[kc * 128 + idx];
        __syncthreads();
#pragma unroll 4
        for (int k = 0; k < 32; ++k) {
            float af[8];
#pragma unroll
            for (int i = 0; i < 8; ++i) af[i] = shA[(ty * 8 + i) * 129 + kc + k];
            float4 b0 = *(const float4*)&shB[k * 128 + tx * 8];
            float4 b1v = *(const float4*)&shB[k * 128 + tx * 8 + 4];
            float bfr[8] = {b0.x, b0.y, b0.z, b0.w, b1v.x, b1v.y, b1v.z, b1v.w};
#pragma unroll
            for (int i = 0; i < 8; ++i)
#pragma unroll
                for (int j = 0; j < 8; ++j) acc[i][j] = fmaf(af[i], bfr[j], acc[i][j]);
        }
    }

    float a = *a_p;
    __syncthreads();  // everyone done reading t before overwriting shA with h
#pragma unroll
    for (int i = 0; i < 8; ++i)
#pragma unroll
        for (int j = 0; j < 8; ++j) {
            float v = acc[i][j] + b1[tx * 8 + j];
            v = (v >= 0.f) ? v : a * v;
            shA[(ty * 8 + i) * 129 + tx * 8 + j] = v;
            acc[i][j] = 0.f;
        }

    for (int kc = 0; kc < HH_; kc += 32) {
        __syncthreads();
        for (int idx = tid; idx < 32 * 128; idx += 256) shB[idx] = W2[kc * 128 + idx];
        __syncthreads();
#pragma unroll 4
        for (int k = 0; k < 32; ++k) {
            float af[8];
#pragma unroll
            for (int i = 0; i < 8; ++i) af[i] = shA[(ty * 8 + i) * 129 + kc + k];
            float4 b0 = *(const float4*)&shB[k * 128 + tx * 8];
            float4 b1v = *(const float4*)&shB[k * 128 + tx * 8 + 4];
            float bfr[8] = {b0.x, b0.y, b0.z, b0.w, b1v.x, b1v.y, b1v.z, b1v.w};
#pragma unroll
            for (int i = 0; i < 8; ++i)
#pragma unroll
                for (int j = 0; j < 8; ++j) acc[i][j] = fmaf(af[i], bfr[j], acc[i][j]);
        }
    }

#pragma unroll
    for (int i = 0; i < 8; ++i) {
        int row = base + ty * 8 + i;
#pragma unroll
        for (int j = 0; j < 8; ++j) {
            float v = acc[i][j] + b2[tx * 8 + j];
            int g = row * HH_ + tx * 8 + j;
            g_z[g] = v;
            out_z[g] = v;
        }
    }
}

// ---------------------------------------------------------------------------
// K4: p = softmax(z @ pW + pb). 16 lanes per node.
__global__ void k_p(const float* __restrict__ pW, const float* __restrict__ pb,
                    float* __restrict__ out_p)
{
    int tid = threadIdx.x;
    int grp = tid >> 4, lane = tid & 15;
    int node = blockIdx.x * 8 + grp;
    const float4* z4 = (const float4*)&g_z[node * HH_];
    float v = pb[lane];
#pragma unroll 8
    for (int k4 = 0; k4 < 32; ++k4) {
        float4 zz = z4[k4];
        int kb = k4 * 4;
        v += zz.x * pW[(kb + 0) * NCC_ + lane];
        v += zz.y * pW[(kb + 1) * NCC_ + lane];
        v += zz.z * pW[(kb + 2) * NCC_ + lane];
        v += zz.w * pW[(kb + 3) * NCC_ + lane];
    }
    float m = v;
#pragma unroll
    for (int off = 8; off > 0; off >>= 1)
        m = fmaxf(m, __shfl_xor_sync(0xffffffffu, m, off, 16));
    float e = expf(v - m);
    float s = e;
#pragma unroll
    for (int off = 8; off > 0; off >>= 1)
        s += __shfl_xor_sync(0xffffffffu, s, off, 16);
    out_p[node * NCC_ + lane] = e / s;
}

// ---------------------------------------------------------------------------
// K5: A_hat = z @ z^T (symmetric: compute upper-triangular tiles, mirror).
__global__ void __launch_bounds__(256, 2)
k_ahat(float* __restrict__ outA)
{
    int bi = blockIdx.y, bj = blockIdx.x;
    if (bj < bi) return;

    __shared__ float shA[128 * 33];
    __shared__ float shBT[32 * 128];
    int tid = threadIdx.x;
    int tx = tid & 15, ty = tid >> 4;

    float acc[8][8];
#pragma unroll
    for (int i = 0; i < 8; ++i)
#pragma unroll
        for (int j = 0; j < 8; ++j) acc[i][j] = 0.f;

    for (int kc = 0; kc < HH_; kc += 32) {
        __syncthreads();
        // A rows (bi), layout [r][33]
        for (int idx = tid; idx < 1024; idx += 256) {
            int r = idx >> 3, k4 = idx & 7;
            float4 v = *(const float4*)&g_z[(bi * 128 + r) * HH_ + kc + k4 * 4];
            shA[r * 33 + k4 * 4 + 0] = v.x;
            shA[r * 33 + k4 * 4 + 1] = v.y;
            shA[r * 33 + k4 * 4 + 2] = v.z;
            shA[r * 33 + k4 * 4 + 3] = v.w;
        }
        // B rows (bj) transposed -> [k][128]
        for (int idx = tid; idx < 1024; idx += 256) {
            int c = idx & 127, k4 = idx >> 7;
            float4 v = *(const float4*)&g_z[(bj * 128 + c) * HH_ + kc + k4 * 4];
            shBT[(k4 * 4 + 0) * 128 + c] = v.x;
            shBT[(k4 * 4 + 1) * 128 + c] = v.y;
            shBT[(k4 * 4 + 2) * 128 + c] = v.z;
            shBT[(k4 * 4 + 3) * 128 + c] = v.w;
        }
        __syncthreads();
#pragma unroll 4
        for (int k = 0; k < 32; ++k) {
            float af[8];
#pragma unroll
            for (int i = 0; i < 8; ++i) af[i] = shA[(ty * 8 + i) * 33 + k];
            float4 b0 = *(const float4*)&shBT[k * 128 + tx * 8];
            float4 b1v = *(const float4*)&shBT[k * 128 + tx * 8 + 4];
            float bfr[8] = {b0.x, b0.y, b0.z, b0.w, b1v.x, b1v.y, b1v.z, b1v.w};
#pragma unroll
            for (int i = 0; i < 8; ++i)
#pragma unroll
                for (int j = 0; j < 8; ++j) acc[i][j] = fmaf(af[i], bfr[j], acc[i][j]);
        }
    }

    const size_t Ns = NN_;
#pragma unroll
    for (int i = 0; i < 8; ++i) {
        size_t row = (size_t)(bi * 128 + ty * 8 + i);
        float4 w0 = make_float4(acc[i][0], acc[i][1], acc[i][2], acc[i][3]);
        float4 w1 = make_float4(acc[i][4], acc[i][5], acc[i][6], acc[i][7]);
        *(float4*)&outA[row * Ns + bj * 128 + tx * 8] = w0;
        *(float4*)&outA[row * Ns + bj * 128 + tx * 8 + 4] = w1;
    }
    if (bi != bj) {
#pragma unroll
        for (int j = 0; j < 8; ++j) {
            size_t col = (size_t)(bj * 128 + tx * 8 + j);
            float4 w0 = make_float4(acc[0][j], acc[1][j], acc[2][j], acc[3][j]);
            float4 w1 = make_float4(acc[4][j], acc[5][j], acc[6][j], acc[7][j]);
            *(float4*)&outA[col * Ns + bi * 128 + ty * 8] = w0;
            *(float4*)&outA[col * Ns + bi * 128 + ty * 8 + 4] = w1;
        }
    }
}

// ---------------------------------------------------------------------------
extern "C" void kernel_launch(void* const* d_in, const int* in_sizes, int n_in,
                              void* d_out, int out_size)
{
    const float* x    = (const float*)d_in[0];
    const float* ea   = (const float*)d_in[1];
    const int*   ei32 = (const int*)  d_in[2];
    const float* neW1 = (const float*)d_in[3];
    const float* neb1 = (const float*)d_in[4];
    const float* nea  = (const float*)d_in[5];
    const float* neW2 = (const float*)d_in[6];
    const float* neb2 = (const float*)d_in[7];
    const float* eeW1 = (const float*)d_in[8];
    const float* eeb1 = (const float*)d_in[9];
    const float* eea  = (const float*)d_in[10];
    const float* eeW2 = (const float*)d_in[11];
    const float* eeb2 = (const float*)d_in[12];
    const float* gW1  = (const float*)d_in[13];
    const float* gb1  = (const float*)d_in[14];
    const float* ga   = (const float*)d_in[15];
    const float* gW2  = (const float*)d_in[16];
    const float* gb2  = (const float*)d_in[17];
    const float* eps  = (const float*)d_in[18];
    const float* pW   = (const float*)d_in[19];
    const float* pb   = (const float*)d_in[20];

    float* out   = (float*)d_out;
    float* out_A = out;                                  // [N, N]
    float* out_p = out + (size_t)NN_ * NN_;              // [N, NC]
    float* out_z = out_p + (size_t)NN_ * NCC_;           // [N, H]

    // dynamic smem sizes
    const int smem_node = (128 * 129 + 32 * 128 + 128 * 33) * 4;           // 99328
    const int smem_edge = (128 * 129 + 32 * 128 + 512 + 512) * 4 + 256 * 4; // 87552
    const int smem_mlp  = (128 * 129 + 32 * 128) * 4;                       // 82432

    cudaFuncSetAttribute(k_node_enc, cudaFuncAttributeMaxDynamicSharedMemorySize, smem_node);
    cudaFuncSetAttribute(k_edge,     cudaFuncAttributeMaxDynamicSharedMemorySize, smem_edge);
    cudaFuncSetAttribute(k_mlp,      cudaFuncAttributeMaxDynamicSharedMemorySize, smem_mlp);

    k_detect<<<1, 32>>>(ei32);
    k_zero_agg<<<512, 256>>>();
    k_node_enc<<<NN_ / 128, 256, smem_node>>>(x, neW1, neb1, nea, neW2, neb2);
    k_edge<<<EE_ / 128, 256, smem_edge>>>(ea, ei32, eeW1, eeb1, eea, eeW2, eeb2);
    k_mlp<<<NN_ / 128, 256, smem_mlp>>>(gW1, gb1, ga, gW2, gb2, eps, out_z);
    k_p<<<NN_ / 8, 128>>>(pW, pb, out_p);
    k_ahat<<<dim3(NN_ / 128, NN_ / 128), 256>>>(out_A);
}

// round 5
// speedup vs baseline: 1.2909x; 1.2909x over previous
#include <cuda_runtime.h>
#include <cuda_fp16.h>
#include <cstdint>

// Problem constants
#define NN_ 8192          // nodes
#define EE_ 524288        // edges
#define HH_ 128           // hidden
#define IND_ 32           // in_dim
#define NCC_ 16           // classes

// Device scratch (static, no allocations)
__device__ __align__(16) float g_cx[NN_ * HH_];    // coded_x
__device__ __align__(16) float g_agg[NN_ * HH_];   // segment-sum accumulator
__device__ __align__(16) float g_z[NN_ * HH_];     // z (fp32, for k_p)
__device__ __align__(16) __half g_zh[NN_ * HH_];   // z hi (fp16)
__device__ __align__(16) __half g_zl[NN_ * HH_];   // z lo (fp16 residual)
__device__ __align__(16) __half g_W2h[HH_ * HH_];  // eeW2 transposed [n][k] hi
__device__ __align__(16) __half g_W2l[HH_ * HH_];  // eeW2 transposed [n][k] lo
__device__ int g_is64;

// ---------------------------------------------------------------------------
__device__ __forceinline__ void red_add_v4(float* addr, float x, float y, float z, float w) {
    asm volatile("red.global.add.v4.f32 [%0], {%1,%2,%3,%4};"
                 :: "l"(addr), "f"(x), "f"(y), "f"(z), "f"(w) : "memory");
}

__device__ __forceinline__ uint32_t smem_u32(const void* p) {
    return (uint32_t)__cvta_generic_to_shared(p);
}

__device__ __forceinline__ void ldmx4(uint32_t r[4], uint32_t addr) {
    asm volatile("ldmatrix.sync.aligned.m8n8.x4.shared.b16 {%0,%1,%2,%3}, [%4];"
                 : "=r"(r[0]), "=r"(r[1]), "=r"(r[2]), "=r"(r[3]) : "r"(addr));
}

__device__ __forceinline__ void mma16816(float c[4], const uint32_t a[4],
                                         uint32_t b0, uint32_t b1) {
    asm volatile("mma.sync.aligned.m16n8k16.row.col.f32.f16.f16.f32 "
                 "{%0,%1,%2,%3}, {%4,%5,%6,%7}, {%8,%9}, {%0,%1,%2,%3};"
                 : "+f"(c[0]), "+f"(c[1]), "+f"(c[2]), "+f"(c[3])
                 : "r"(a[0]), "r"(a[1]), "r"(a[2]), "r"(a[3]), "r"(b0), "r"(b1));
}

// 128x128x128 tile GEMM with fp16 hi/lo 3-term split.
// A in smem [m=128][k=136pad] (hi, lo); B in smem [n=128][k=136pad] (hi, lo).
// Warp layout: 8 warps as 2(m) x 4(n); warp tile 64x32; acc[4mt][4nt][4].
#define LDAH_ 136
__device__ __forceinline__ void mma_tile_3x(
    float acc[4][4][4], uint32_t sAh, uint32_t sAl, uint32_t sBh, uint32_t sBl,
    int wm, int wn, int lane)
{
    int lrow = lane & 15;
    int lcol = (lane >> 4) * 8;
#pragma unroll 1
    for (int ks = 0; ks < 8; ++ks) {
        int kk = ks * 16;
        uint32_t ah[4][4], al[4][4], bh[2][4], bl[2][4];
#pragma unroll
        for (int mt = 0; mt < 4; ++mt) {
            uint32_t off = (uint32_t)(((wm + mt * 16 + lrow) * LDAH_ + kk + lcol) * 2);
            ldmx4(ah[mt], sAh + off);
            ldmx4(al[mt], sAl + off);
        }
#pragma unroll
        for (int bt = 0; bt < 2; ++bt) {
            uint32_t off = (uint32_t)(((wn + bt * 16 + lrow) * LDAH_ + kk + lcol) * 2);
            ldmx4(bh[bt], sBh + off);
            ldmx4(bl[bt], sBl + off);
        }
#pragma unroll
        for (int mt = 0; mt < 4; ++mt)
#pragma unroll
            for (int nt = 0; nt < 4; ++nt) {
                int bt = nt >> 1, sel = nt & 1;
                mma16816(acc[mt][nt], ah[mt], bh[bt][sel], bh[bt][sel + 2]);
                mma16816(acc[mt][nt], ah[mt], bl[bt][sel], bl[bt][sel + 2]);
                mma16816(acc[mt][nt], al[mt], bh[bt][sel], bh[bt][sel + 2]);
            }
    }
}

// Stage mma-layout accumulators to smem fp32 [128][132]
__device__ __forceinline__ void stage_acc(float* shAcc, float acc[4][4][4],
                                          int wm, int wn, int lane)
{
#pragma unroll
    for (int mt = 0; mt < 4; ++mt)
#pragma unroll
        for (int nt = 0; nt < 4; ++nt) {
            int r = wm + mt * 16 + (lane >> 2);
            int c = wn + nt * 8 + (lane & 3) * 2;
            shAcc[r * 132 + c] = acc[mt][nt][0];
            shAcc[r * 132 + c + 1] = acc[mt][nt][1];
            shAcc[(r + 8) * 132 + c] = acc[mt][nt][2];
            shAcc[(r + 8) * 132 + c + 1] = acc[mt][nt][3];
        }
}

// ---------------------------------------------------------------------------
// K0: detect int64 vs int32 edge_index layout.
__global__ void k_detect(const int* __restrict__ ei32) {
    if (threadIdx.x == 0) {
        int all0 = 1;
        for (int i = 0; i < 64; ++i) {
            if (ei32[2 * i + 1] != 0) { all0 = 0; break; }
        }
        g_is64 = all0;
    }
}

__global__ void k_zero_agg() {
    int idx = blockIdx.x * blockDim.x + threadIdx.x;
    float4* p = reinterpret_cast<float4*>(g_agg);
    int n4 = NN_ * HH_ / 4;
    for (int i = idx; i < n4; i += gridDim.x * blockDim.x)
        p[i] = make_float4(0.f, 0.f, 0.f, 0.f);
}

// Kw: split eeW2 [k][n] into transposed fp16 hi/lo [n][k]
__global__ void k_split_w2(const float* __restrict__ W2) {
    int idx = blockIdx.x * 256 + threadIdx.x;   // 16384 total
    int k = idx >> 7, n = idx & 127;
    float v = W2[k * 128 + n];
    __half h = __float2half_rn(v);
    g_W2h[n * 128 + k] = h;
    g_W2l[n * 128 + k] = __float2half_rn(v - __half2float(h));
}

// ---------------------------------------------------------------------------
// K1: node encoder (FFMA; tiny: 0.3 GFLOP)
__global__ void __launch_bounds__(256, 2)
k_node_enc(const float* __restrict__ x,
           const float* __restrict__ W1, const float* __restrict__ b1,
           const float* __restrict__ a_p,
           const float* __restrict__ W2, const float* __restrict__ b2)
{
    extern __shared__ float sm[];
    float* shA = sm;
    float* shB = shA + 128 * 129;
    float* shX = shB + 32 * 128;
    int tid = threadIdx.x;
    int tx = tid & 15, ty = tid >> 4;
    int base = blockIdx.x * 128;

    for (int idx = tid; idx < 128 * IND_; idx += 256) {
        int r = idx >> 5, k = idx & 31;
        shX[r * 33 + k] = x[(base + r) * IND_ + k];
    }
    for (int idx = tid; idx < IND_ * 128; idx += 256) shB[idx] = W1[idx];
    __syncthreads();

    float acc[8][8];
#pragma unroll
    for (int i = 0; i < 8; ++i)
#pragma unroll
        for (int j = 0; j < 8; ++j) acc[i][j] = 0.f;

#pragma unroll 4
    for (int k = 0; k < IND_; ++k) {
        float af[8];
#pragma unroll
        for (int i = 0; i < 8; ++i) af[i] = shX[(ty * 8 + i) * 33 + k];
        float4 b0 = *(const float4*)&shB[k * 128 + tx * 8];
        float4 b1v = *(const float4*)&shB[k * 128 + tx * 8 + 4];
        float bfr[8] = {b0.x, b0.y, b0.z, b0.w, b1v.x, b1v.y, b1v.z, b1v.w};
#pragma unroll
        for (int i = 0; i < 8; ++i)
#pragma unroll
            for (int j = 0; j < 8; ++j) acc[i][j] = fmaf(af[i], bfr[j], acc[i][j]);
    }

    float a = *a_p;
#pragma unroll
    for (int i = 0; i < 8; ++i)
#pragma unroll
        for (int j = 0; j < 8; ++j) {
            float v = acc[i][j] + b1[tx * 8 + j];
            v = (v >= 0.f) ? v : a * v;
            shA[(ty * 8 + i) * 129 + tx * 8 + j] = v;
            acc[i][j] = 0.f;
        }

    for (int kc = 0; kc < HH_; kc += 32) {
        __syncthreads();
        for (int idx = tid; idx < 32 * 128; idx += 256) shB[idx] = W2[kc * 128 + idx];
        __syncthreads();
#pragma unroll 4
        for (int k = 0; k < 32; ++k) {
            float af[8];
#pragma unroll
            for (int i = 0; i < 8; ++i) af[i] = shA[(ty * 8 + i) * 129 + kc + k];
            float4 b0 = *(const float4*)&shB[k * 128 + tx * 8];
            float4 b1v = *(const float4*)&shB[k * 128 + tx * 8 + 4];
            float bfr[8] = {b0.x, b0.y, b0.z, b0.w, b1v.x, b1v.y, b1v.z, b1v.w};
#pragma unroll
            for (int i = 0; i < 8; ++i)
#pragma unroll
                for (int j = 0; j < 8; ++j) acc[i][j] = fmaf(af[i], bfr[j], acc[i][j]);
        }
    }
#pragma unroll
    for (int i = 0; i < 8; ++i) {
        int row = base + ty * 8 + i;
#pragma unroll
        for (int j = 0; j < 8; ++j)
            g_cx[row * HH_ + tx * 8 + j] = acc[i][j] + b2[tx * 8 + j];
    }
}

// ---------------------------------------------------------------------------
// K2: fused edge pipeline with fp16 split tensor-core GEMM.
// smem layout (bytes):
//   [0,      34816)  shAh  h1 hi  [128][136] fp16       } overlaid by
//   [34816,  69632)  shAl  h1 lo                        } shAcc [128][132] fp32
//   [69632, 104448)  shBh  W2^T hi [n][k]
//   [104448,139264)  shBl  W2^T lo
//   [139264, ...)    shEA(512f) shW1(512f) shSrc(128i) shDst(128i)
__global__ void __launch_bounds__(256, 1)
k_edge(const float* __restrict__ ea, const int* __restrict__ ei32,
       const float* __restrict__ W1, const float* __restrict__ b1,
       const float* __restrict__ a_p, const float* __restrict__ b2)
{
    extern __shared__ char smc[];
    __half* shAh = (__half*)smc;
    __half* shAl = shAh + 128 * LDAH_;
    __half* shBh = (__half*)(smc + 69632);
    __half* shBl = shBh + 128 * LDAH_;
    float* shEA = (float*)(smc + 139264);
    float* shW1 = shEA + 512;
    int* shSrc = (int*)(shW1 + 512);
    int* shDst = shSrc + 128;

    int tid = threadIdx.x;
    int e0 = blockIdx.x * 128;

    if (tid < 128) {
        if (g_is64) {
            shSrc[tid] = ei32[2 * (e0 + tid)];
            shDst[tid] = ei32[2 * (EE_ + e0 + tid)];
        } else {
            shSrc[tid] = ei32[e0 + tid];
            shDst[tid] = ei32[EE_ + e0 + tid];
        }
    }
    for (int idx = tid; idx < 512; idx += 256) {
        shEA[idx] = ea[e0 * 4 + idx];
        shW1[idx] = W1[idx];
    }
    // W2 hi/lo tiles ([n][k] row-major, vectorized 8 halves)
    {
        const uint4* wh4 = (const uint4*)g_W2h;
        const uint4* wl4 = (const uint4*)g_W2l;
        for (int idx = tid; idx < 2048; idx += 256) {
            int n = idx >> 4, ko = (idx & 15) * 8;
            *(uint4*)&shBh[n * LDAH_ + ko] = wh4[idx];
            *(uint4*)&shBl[n * LDAH_ + ko] = wl4[idx];
        }
    }
    __syncthreads();

    // h1 = prelu(ea@W1 + b1), split to fp16 hi/lo
    float a = *a_p;
    for (int idx = tid; idx < 16384; idx += 256) {
        int e = idx >> 7, j = idx & 127;
        float v = b1[j];
#pragma unroll
        for (int k = 0; k < 4; ++k) v = fmaf(shEA[e * 4 + k], shW1[k * 128 + j], v);
        v = (v >= 0.f) ? v : a * v;
        __half h = __float2half_rn(v);
        shAh[e * LDAH_ + j] = h;
        shAl[e * LDAH_ + j] = __float2half_rn(v - __half2float(h));
    }
    __syncthreads();

    float acc[4][4][4] = {};
    int lane = tid & 31, w = tid >> 5;
    int wm = (w >> 2) * 64, wn = (w & 3) * 32;
    mma_tile_3x(acc, smem_u32(shAh), smem_u32(shAl), smem_u32(shBh), smem_u32(shBl),
                wm, wn, lane);

    __syncthreads();                 // all ldmatrix reads done before overwrite
    float* shAcc = (float*)smc;
    stage_acc(shAcc, acc, wm, wn, lane);
    __syncthreads();

    int tx = tid & 15, ty = tid >> 4;
    float4 bv0 = *(const float4*)&b2[tx * 8];
    float4 bv1 = *(const float4*)&b2[tx * 8 + 4];
#pragma unroll
    for (int i = 0; i < 8; ++i) {
        int r = ty * 8 + i;
        int s = shSrc[r], d = shDst[r];
        const float4 cx0 = *(const float4*)&g_cx[s * HH_ + tx * 8];
        const float4 cx1 = *(const float4*)&g_cx[s * HH_ + tx * 8 + 4];
        const float* row = &shAcc[r * 132 + tx * 8];
        float m0 = fmaxf(0.f, row[0] + bv0.x + cx0.x);
        float m1 = fmaxf(0.f, row[1] + bv0.y + cx0.y);
        float m2 = fmaxf(0.f, row[2] + bv0.z + cx0.z);
        float m3 = fmaxf(0.f, row[3] + bv0.w + cx0.w);
        float m4 = fmaxf(0.f, row[4] + bv1.x + cx1.x);
        float m5 = fmaxf(0.f, row[5] + bv1.y + cx1.y);
        float m6 = fmaxf(0.f, row[6] + bv1.z + cx1.z);
        float m7 = fmaxf(0.f, row[7] + bv1.w + cx1.w);
        red_add_v4(&g_agg[d * HH_ + tx * 8], m0, m1, m2, m3);
        red_add_v4(&g_agg[d * HH_ + tx * 8 + 4], m4, m5, m6, m7);
    }
}

// ---------------------------------------------------------------------------
// K3: GINE mlp (loop invariant -> once). FFMA (0.5 GFLOP). Epilogue stores
// z fp32 + fp16 hi/lo split for A_hat.
__global__ void __launch_bounds__(256, 2)
k_mlp(const float* __restrict__ W1, const float* __restrict__ b1,
      const float* __restrict__ a_p,
      const float* __restrict__ W2, const float* __restrict__ b2,
      const float* __restrict__ eps_p, float* __restrict__ out_z)
{
    extern __shared__ float sm[];
    float* shA = sm;
    float* shB = shA + 128 * 129;
    int tid = threadIdx.x;
    int tx = tid & 15, ty = tid >> 4;
    int base = blockIdx.x * 128;

    float ep = 1.0f + *eps_p;
    for (int idx = tid; idx < 128 * 128; idx += 256) {
        int r = idx >> 7, k = idx & 127;
        int g = (base + r) * HH_ + k;
        shA[r * 129 + k] = ep * g_cx[g] + g_agg[g];
    }

    float acc[8][8];
#pragma unroll
    for (int i = 0; i < 8; ++i)
#pragma unroll
        for (int j = 0; j < 8; ++j) acc[i][j] = 0.f;

    for (int kc = 0; kc < HH_; kc += 32) {
        __syncthreads();
        for (int idx = tid; idx < 32 * 128; idx += 256) shB[idx] = W1[kc * 128 + idx];
        __syncthreads();
#pragma unroll 4
        for (int k = 0; k < 32; ++k) {
            float af[8];
#pragma unroll
            for (int i = 0; i < 8; ++i) af[i] = shA[(ty * 8 + i) * 129 + kc + k];
            float4 b0 = *(const float4*)&shB[k * 128 + tx * 8];
            float4 b1v = *(const float4*)&shB[k * 128 + tx * 8 + 4];
            float bfr[8] = {b0.x, b0.y, b0.z, b0.w, b1v.x, b1v.y, b1v.z, b1v.w};
#pragma unroll
            for (int i = 0; i < 8; ++i)
#pragma unroll
                for (int j = 0; j < 8; ++j) acc[i][j] = fmaf(af[i], bfr[j], acc[i][j]);
        }
    }

    float a = *a_p;
    __syncthreads();
#pragma unroll
    for (int i = 0; i < 8; ++i)
#pragma unroll
        for (int j = 0; j < 8; ++j) {
            float v = acc[i][j] + b1[tx * 8 + j];
            v = (v >= 0.f) ? v : a * v;
            shA[(ty * 8 + i) * 129 + tx * 8 + j] = v;
            acc[i][j] = 0.f;
        }

    for (int kc = 0; kc < HH_; kc += 32) {
        __syncthreads();
        for (int idx = tid; idx < 32 * 128; idx += 256) shB[idx] = W2[kc * 128 + idx];
        __syncthreads();
#pragma unroll 4
        for (int k = 0; k < 32; ++k) {
            float af[8];
#pragma unroll
            for (int i = 0; i < 8; ++i) af[i] = shA[(ty * 8 + i) * 129 + kc + k];
            float4 b0 = *(const float4*)&shB[k * 128 + tx * 8];
            float4 b1v = *(const float4*)&shB[k * 128 + tx * 8 + 4];
            float bfr[8] = {b0.x, b0.y, b0.z, b0.w, b1v.x, b1v.y, b1v.z, b1v.w};
#pragma unroll
            for (int i = 0; i < 8; ++i)
#pragma unroll
                for (int j = 0; j < 8; ++j) acc[i][j] = fmaf(af[i], bfr[j], acc[i][j]);
        }
    }

#pragma unroll
    for (int i = 0; i < 8; ++i) {
        int row = base + ty * 8 + i;
#pragma unroll
        for (int j = 0; j < 8; ++j) {
            float v = acc[i][j] + b2[tx * 8 + j];
            int g = row * HH_ + tx * 8 + j;
            g_z[g] = v;
            out_z[g] = v;
            __half h = __float2half_rn(v);
            g_zh[g] = h;
            g_zl[g] = __float2half_rn(v - __half2float(h));
        }
    }
}

// ---------------------------------------------------------------------------
// K4: p = softmax(z @ pW + pb)
__global__ void k_p(const float* __restrict__ pW, const float* __restrict__ pb,
                    float* __restrict__ out_p)
{
    int tid = threadIdx.x;
    int grp = tid >> 4, lane = tid & 15;
    int node = blockIdx.x * 8 + grp;
    const float4* z4 = (const float4*)&g_z[node * HH_];
    float v = pb[lane];
#pragma unroll 8
    for (int k4 = 0; k4 < 32; ++k4) {
        float4 zz = z4[k4];
        int kb = k4 * 4;
        v += zz.x * pW[(kb + 0) * NCC_ + lane];
        v += zz.y * pW[(kb + 1) * NCC_ + lane];
        v += zz.z * pW[(kb + 2) * NCC_ + lane];
        v += zz.w * pW[(kb + 3) * NCC_ + lane];
    }
    float m = v;
#pragma unroll
    for (int off = 8; off > 0; off >>= 1)
        m = fmaxf(m, __shfl_xor_sync(0xffffffffu, m, off, 16));
    float e = expf(v - m);
    float s = e;
#pragma unroll
    for (int off = 8; off > 0; off >>= 1)
        s += __shfl_xor_sync(0xffffffffu, s, off, 16);
    out_p[node * NCC_ + lane] = e / s;
}

// ---------------------------------------------------------------------------
// K5: A_hat = z @ z^T, tensor-core fp16-split, symmetric (mirror writes).
// smem: shAh/shAl (rows bi), shBh/shBl (rows bj); shAcc overlays shAh/shAl.
__global__ void __launch_bounds__(256, 1)
k_ahat(float* __restrict__ outA)
{
    int bi = blockIdx.y, bj = blockIdx.x;
    if (bj < bi) return;

    extern __shared__ char smc[];
    __half* shAh = (__half*)smc;
    __half* shAl = shAh + 128 * LDAH_;
    __half* shBh = (__half*)(smc + 69632);
    __half* shBl = shBh + 128 * LDAH_;
    int tid = threadIdx.x;

    const uint4* zh4 = (const uint4*)g_zh;
    const uint4* zl4 = (const uint4*)g_zl;
    for (int idx = tid; idx < 2048; idx += 256) {
        int r = idx >> 4, kv = idx & 15;
        int ko = kv * 8;
        *(uint4*)&shAh[r * LDAH_ + ko] = zh4[(bi * 128 + r) * 16 + kv];
        *(uint4*)&shAl[r * LDAH_ + ko] = zl4[(bi * 128 + r) * 16 + kv];
        *(uint4*)&shBh[r * LDAH_ + ko] = zh4[(bj * 128 + r) * 16 + kv];
        *(uint4*)&shBl[r * LDAH_ + ko] = zl4[(bj * 128 + r) * 16 + kv];
    }
    __syncthreads();

    float acc[4][4][4] = {};
    int lane = tid & 31, w = tid >> 5;
    int wm = (w >> 2) * 64, wn = (w & 3) * 32;
    mma_tile_3x(acc, smem_u32(shAh), smem_u32(shAl), smem_u32(shBh), smem_u32(shBl),
                wm, wn, lane);

    __syncthreads();
    float* shAcc = (float*)smc;
    stage_acc(shAcc, acc, wm, wn, lane);
    __syncthreads();

    int tx = tid & 15, ty = tid >> 4;
    const size_t Ns = NN_;
#pragma unroll
    for (int i = 0; i < 8; ++i) {
        int r = ty * 8 + i;
        const float* row = &shAcc[r * 132 + tx * 8];
        float4 w0 = make_float4(row[0], row[1], row[2], row[3]);
        float4 w1 = make_float4(row[4], row[5], row[6], row[7]);
        size_t go = (size_t)(bi * 128 + r) * Ns + bj * 128 + tx * 8;
        *(float4*)&outA[go] = w0;
        *(float4*)&outA[go + 4] = w1;
    }
    if (bi != bj) {
#pragma unroll
        for (int i = 0; i < 8; ++i) {
            int u = ty * 8 + i;   // mirror-block row (bj side)
            float4 w0 = make_float4(shAcc[(tx * 8 + 0) * 132 + u],
                                    shAcc[(tx * 8 + 1) * 132 + u],
                                    shAcc[(tx * 8 + 2) * 132 + u],
                                    shAcc[(tx * 8 + 3) * 132 + u]);
            float4 w1 = make_float4(shAcc[(tx * 8 + 4) * 132 + u],
                                    shAcc[(tx * 8 + 5) * 132 + u],
                                    shAcc[(tx * 8 + 6) * 132 + u],
                                    shAcc[(tx * 8 + 7) * 132 + u]);
            size_t go = (size_t)(bj * 128 + u) * Ns + bi * 128 + tx * 8;
            *(float4*)&outA[go] = w0;
            *(float4*)&outA[go + 4] = w1;
        }
    }
}

// ---------------------------------------------------------------------------
extern "C" void kernel_launch(void* const* d_in, const int* in_sizes, int n_in,
                              void* d_out, int out_size)
{
    const float* x    = (const float*)d_in[0];
    const float* ea   = (const float*)d_in[1];
    const int*   ei32 = (const int*)  d_in[2];
    const float* neW1 = (const float*)d_in[3];
    const float* neb1 = (const float*)d_in[4];
    const float* nea  = (const float*)d_in[5];
    const float* neW2 = (const float*)d_in[6];
    const float* neb2 = (const float*)d_in[7];
    const float* eeW1 = (const float*)d_in[8];
    const float* eeb1 = (const float*)d_in[9];
    const float* eea  = (const float*)d_in[10];
    const float* eeW2 = (const float*)d_in[11];
    const float* eeb2 = (const float*)d_in[12];
    const float* gW1  = (const float*)d_in[13];
    const float* gb1  = (const float*)d_in[14];
    const float* ga   = (const float*)d_in[15];
    const float* gW2  = (const float*)d_in[16];
    const float* gb2  = (const float*)d_in[17];
    const float* eps  = (const float*)d_in[18];
    const float* pW   = (const float*)d_in[19];
    const float* pb   = (const float*)d_in[20];

    float* out   = (float*)d_out;
    float* out_A = out;                                  // [N, N]
    float* out_p = out + (size_t)NN_ * NN_;              // [N, NC]
    float* out_z = out_p + (size_t)NN_ * NCC_;           // [N, H]

    const int smem_node = (128 * 129 + 32 * 128 + 128 * 33) * 4;  // 99328
    const int smem_mlp  = (128 * 129 + 32 * 128) * 4;             // 82432
    const int smem_edge = 139264 + (512 + 512 + 128 + 128) * 4;   // 144384
    const int smem_ahat = 139264;

    cudaFuncSetAttribute(k_node_enc, cudaFuncAttributeMaxDynamicSharedMemorySize, smem_node);
    cudaFuncSetAttribute(k_mlp,      cudaFuncAttributeMaxDynamicSharedMemorySize, smem_mlp);
    cudaFuncSetAttribute(k_edge,     cudaFuncAttributeMaxDynamicSharedMemorySize, smem_edge);
    cudaFuncSetAttribute(k_ahat,     cudaFuncAttributeMaxDynamicSharedMemorySize, smem_ahat);

    k_detect<<<1, 32>>>(ei32);
    k_zero_agg<<<512, 256>>>();
    k_split_w2<<<64, 256>>>(eeW2);
    k_node_enc<<<NN_ / 128, 256, smem_node>>>(x, neW1, neb1, nea, neW2, neb2);
    k_edge<<<EE_ / 128, 256, smem_edge>>>(ea, ei32, eeW1, eeb1, eea, eeb2);
    k_mlp<<<NN_ / 128, 256, smem_mlp>>>(gW1, gb1, ga, gW2, gb2, eps, out_z);
    k_p<<<NN_ / 8, 128>>>(pW, pb, out_p);
    k_ahat<<<dim3(NN_ / 128, NN_ / 128), 256, smem_ahat>>>(out_A);
}

// round 8
// speedup vs baseline: 1.3755x; 1.0656x over previous
#include <cuda_runtime.h>
#include <cuda_fp16.h>
#include <cstdint>

#define NN_ 8192
#define EE_ 524288
#define HH_ 128
#define IND_ 32
#define NCC_ 16

// Device scratch (static, no allocations)
__device__ __align__(16) float g_cx[NN_ * HH_];
__device__ __align__(16) float g_agg[NN_ * HH_];
__device__ __align__(16) float g_z[NN_ * HH_];
__device__ __align__(16) __half g_zh[NN_ * HH_];
__device__ __align__(16) __half g_zl[NN_ * HH_];
__device__ __align__(16) __half g_W2h[HH_ * HH_];  // eeW2^T [n][k] hi
__device__ __align__(16) __half g_W2l[HH_ * HH_];  // eeW2^T [n][k] lo
__device__ int g_is64;

// ---------------------------------------------------------------------------
__device__ __forceinline__ void red_add_v4(float* addr, float x, float y, float z, float w) {
    asm volatile("red.global.add.v4.f32 [%0], {%1,%2,%3,%4};"
                 :: "l"(addr), "f"(x), "f"(y), "f"(z), "f"(w) : "memory");
}
__device__ __forceinline__ uint32_t smem_u32(const void* p) {
    return (uint32_t)__cvta_generic_to_shared(p);
}
__device__ __forceinline__ void ldmx4(uint32_t r[4], uint32_t addr) {
    asm volatile("ldmatrix.sync.aligned.m8n8.x4.shared.b16 {%0,%1,%2,%3}, [%4];"
                 : "=r"(r[0]), "=r"(r[1]), "=r"(r[2]), "=r"(r[3]) : "r"(addr));
}
__device__ __forceinline__ void mma16816(float c[4], const uint32_t a[4],
                                         uint32_t b0, uint32_t b1) {
    asm volatile("mma.sync.aligned.m16n8k16.row.col.f32.f16.f16.f32 "
                 "{%0,%1,%2,%3}, {%4,%5,%6,%7}, {%8,%9}, {%0,%1,%2,%3};"
                 : "+f"(c[0]), "+f"(c[1]), "+f"(c[2]), "+f"(c[3])
                 : "r"(a[0]), "r"(a[1]), "r"(a[2]), "r"(a[3]), "r"(b0), "r"(b1));
}

// 128x128x128 tile GEMM, fp16 hi/lo 3-term split. A,B in smem [128][136] fp16.
// 8 warps as 2(m) x 4(n); warp tile 64x32; acc[4][4][4].
#define LDAH_ 136
__device__ __forceinline__ void mma_tile_3x(
    float acc[4][4][4], uint32_t sAh, uint32_t sAl, uint32_t sBh, uint32_t sBl,
    int wm, int wn, int lane)
{
    int lrow = lane & 15;
    int lcol = (lane >> 4) * 8;
#pragma unroll 1
    for (int ks = 0; ks < 8; ++ks) {
        int kk = ks * 16;
        uint32_t ah[4][4], al[4][4], bh[2][4], bl[2][4];
#pragma unroll
        for (int mt = 0; mt < 4; ++mt) {
            uint32_t off = (uint32_t)(((wm + mt * 16 + lrow) * LDAH_ + kk + lcol) * 2);
            ldmx4(ah[mt], sAh + off);
            ldmx4(al[mt], sAl + off);
        }
#pragma unroll
        for (int bt = 0; bt < 2; ++bt) {
            uint32_t off = (uint32_t)(((wn + bt * 16 + lrow) * LDAH_ + kk + lcol) * 2);
            ldmx4(bh[bt], sBh + off);
            ldmx4(bl[bt], sBl + off);
        }
#pragma unroll
        for (int mt = 0; mt < 4; ++mt)
#pragma unroll
            for (int nt = 0; nt < 4; ++nt) {
                int bt = nt >> 1, sel = nt & 1;
                mma16816(acc[mt][nt], ah[mt], bh[bt][sel], bh[bt][sel + 2]);
                mma16816(acc[mt][nt], ah[mt], bl[bt][sel], bl[bt][sel + 2]);
                mma16816(acc[mt][nt], al[mt], bh[bt][sel], bh[bt][sel + 2]);
            }
    }
}

__device__ __forceinline__ void stage_acc(float* shAcc, float acc[4][4][4],
                                          int wm, int wn, int lane)
{
#pragma unroll
    for (int mt = 0; mt < 4; ++mt)
#pragma unroll
        for (int nt = 0; nt < 4; ++nt) {
            int r = wm + mt * 16 + (lane >> 2);
            int c = wn + nt * 8 + (lane & 3) * 2;
            shAcc[r * 132 + c] = acc[mt][nt][0];
            shAcc[r * 132 + c + 1] = acc[mt][nt][1];
            shAcc[(r + 8) * 132 + c] = acc[mt][nt][2];
            shAcc[(r + 8) * 132 + c + 1] = acc[mt][nt][3];
        }
}

// ---------------------------------------------------------------------------
// K_prep: detect int64 layout + zero g_agg
__global__ void k_prep(const int* __restrict__ ei32) {
    if (blockIdx.x == 0 && threadIdx.x == 0) {
        int all0 = 1;
        for (int i = 0; i < 64; ++i)
            if (ei32[2 * i + 1] != 0) { all0 = 0; break; }
        g_is64 = all0;
    }
    int idx = blockIdx.x * blockDim.x + threadIdx.x;
    float4* p = reinterpret_cast<float4*>(g_agg);
    int n4 = NN_ * HH_ / 4;
    for (int i = idx; i < n4; i += gridDim.x * blockDim.x)
        p[i] = make_float4(0.f, 0.f, 0.f, 0.f);
}

// K_split: eeW2 [k][n] -> transposed fp16 hi/lo [n][k]
__global__ void k_split_w2(const float* __restrict__ W2) {
    int idx = blockIdx.x * 256 + threadIdx.x;
    int k = idx >> 7, n = idx & 127;
    float v = W2[k * 128 + n];
    __half h = __float2half_rn(v);
    g_W2h[n * 128 + k] = h;
    g_W2l[n * 128 + k] = __float2half_rn(v - __half2float(h));
}

// ---------------------------------------------------------------------------
// K_node: 256 CTAs x 32 rows (occupancy fix)
__global__ void __launch_bounds__(256)
k_node_enc(const float* __restrict__ x,
           const float* __restrict__ W1, const float* __restrict__ b1,
           const float* __restrict__ a_p,
           const float* __restrict__ W2, const float* __restrict__ b2)
{
    __shared__ float shA[32 * 129];
    __shared__ float shB[32 * 128];
    __shared__ float shX[32 * 33];
    int tid = threadIdx.x;
    int tx = tid & 15, ty = tid >> 4;
    int base = blockIdx.x * 32;

    for (int idx = tid; idx < 32 * 32; idx += 256) {
        int r = idx >> 5, k = idx & 31;
        shX[r * 33 + k] = x[(base + r) * IND_ + k];
    }
    for (int idx = tid; idx < 32 * 128; idx += 256) shB[idx] = W1[idx];
    __syncthreads();

    float acc[2][8];
#pragma unroll
    for (int i = 0; i < 2; ++i)
#pragma unroll
        for (int j = 0; j < 8; ++j) acc[i][j] = 0.f;

#pragma unroll 4
    for (int k = 0; k < 32; ++k) {
        float a0 = shX[(ty * 2 + 0) * 33 + k];
        float a1 = shX[(ty * 2 + 1) * 33 + k];
        float4 b0 = *(const float4*)&shB[k * 128 + tx * 8];
        float4 b1v = *(const float4*)&shB[k * 128 + tx * 8 + 4];
        float bfr[8] = {b0.x, b0.y, b0.z, b0.w, b1v.x, b1v.y, b1v.z, b1v.w};
#pragma unroll
        for (int j = 0; j < 8; ++j) {
            acc[0][j] = fmaf(a0, bfr[j], acc[0][j]);
            acc[1][j] = fmaf(a1, bfr[j], acc[1][j]);
        }
    }
    float a = *a_p;
#pragma unroll
    for (int i = 0; i < 2; ++i)
#pragma unroll
        for (int j = 0; j < 8; ++j) {
            float v = acc[i][j] + b1[tx * 8 + j];
            v = (v >= 0.f) ? v : a * v;
            shA[(ty * 2 + i) * 129 + tx * 8 + j] = v;
            acc[i][j] = 0.f;
        }

    for (int kc = 0; kc < HH_; kc += 32) {
        __syncthreads();
        for (int idx = tid; idx < 32 * 128; idx += 256) shB[idx] = W2[kc * 128 + idx];
        __syncthreads();
#pragma unroll 4
        for (int k = 0; k < 32; ++k) {
            float a0 = shA[(ty * 2 + 0) * 129 + kc + k];
            float a1 = shA[(ty * 2 + 1) * 129 + kc + k];
            float4 b0 = *(const float4*)&shB[k * 128 + tx * 8];
            float4 b1v = *(const float4*)&shB[k * 128 + tx * 8 + 4];
            float bfr[8] = {b0.x, b0.y, b0.z, b0.w, b1v.x, b1v.y, b1v.z, b1v.w};
#pragma unroll
            for (int j = 0; j < 8; ++j) {
                acc[0][j] = fmaf(a0, bfr[j], acc[0][j]);
                acc[1][j] = fmaf(a1, bfr[j], acc[1][j]);
            }
        }
    }
#pragma unroll
    for (int i = 0; i < 2; ++i) {
        int row = base + ty * 2 + i;
#pragma unroll
        for (int j = 0; j < 8; ++j)
            g_cx[row * HH_ + tx * 8 + j] = acc[i][j] + b2[tx * 8 + j];
    }
}

// ---------------------------------------------------------------------------
// K_edge: PERSISTENT fused edge pipeline (HMMA fp16-split).
// Weights loaded ONCE per CTA; each CTA loops over tiles stride-gridDim.
// smem layout (bytes):
//   0       shAh  h1 hi [128][136] f16   (34816)
//   34816   shAl  h1 lo                  (34816)
//   69632   shBh  W2^T hi [n][k]         (34816)
//   104448  shBl  W2^T lo                (34816)
//   139264  shStage [128][132] f32       (67584)
//   206848  shEA  [128][4] f32           (2048)
//   208896  shW1  [4][128] f32           (2048)
//   210944  shB1c [128] f32              (512)
//   211456  shB2c [128] f32              (512)
//   211968  shSrc [128] i32              (512)
//   212480  shDst [128] i32              (512)    total 212992
__global__ void __launch_bounds__(256, 1)
k_edge(const float* __restrict__ ea, const int* __restrict__ ei32,
       const float* __restrict__ W1, const float* __restrict__ b1,
       const float* __restrict__ a_p, const float* __restrict__ b2,
       int ntiles)
{
    extern __shared__ char smc[];
    __half* shAh = (__half*)smc;
    __half* shAl = (__half*)(smc + 34816);
    __half* shBh = (__half*)(smc + 69632);
    __half* shBl = (__half*)(smc + 104448);
    float* shStage = (float*)(smc + 139264);
    float* shEA = (float*)(smc + 206848);
    float* shW1 = (float*)(smc + 208896);
    float* shB1c = (float*)(smc + 210944);
    float* shB2c = (float*)(smc + 211456);
    int* shSrc = (int*)(smc + 211968);
    int* shDst = (int*)(smc + 212480);

    int tid = threadIdx.x;
    int tx = tid & 15, ty = tid >> 4;
    int lane = tid & 31, w = tid >> 5;
    int wm = (w >> 2) * 64, wn = (w & 3) * 32;
    int is64 = g_is64;

    // One-time: weights + biases
    {
        const uint4* wh4 = (const uint4*)g_W2h;
        const uint4* wl4 = (const uint4*)g_W2l;
        for (int idx = tid; idx < 2048; idx += 256) {
            int n = idx >> 4, ko = (idx & 15) * 8;
            *(uint4*)&shBh[n * LDAH_ + ko] = wh4[idx];
            *(uint4*)&shBl[n * LDAH_ + ko] = wl4[idx];
        }
        for (int idx = tid; idx < 512; idx += 256) shW1[idx] = W1[idx];
        if (tid < 128) { shB1c[tid] = b1[tid]; shB2c[tid] = b2[tid]; }
    }
    float a = *a_p;
    __syncthreads();

    for (int t = blockIdx.x; t < ntiles; t += gridDim.x) {
        int e0 = t * 128;
        // (a) tile inputs
        if (tid < 128) {
            if (is64) {
                shSrc[tid] = ei32[2 * (e0 + tid)];
                shDst[tid] = ei32[2 * (EE_ + e0 + tid)];
            } else {
                shSrc[tid] = ei32[e0 + tid];
                shDst[tid] = ei32[EE_ + e0 + tid];
            }
        }
        for (int idx = tid; idx < 512; idx += 256) shEA[idx] = ea[e0 * 4 + idx];
        __syncthreads();   // S1

        // grab this thread's src/dst rows into regs (rows ty*8..+7)
        int sreg[8], dreg[8];
#pragma unroll
        for (int i = 0; i < 8; ++i) {
            sreg[i] = shSrc[ty * 8 + i];
            dreg[i] = shDst[ty * 8 + i];
        }

        // h1 = prelu(ea@W1 + b1) -> fp16 hi/lo
        for (int idx = tid; idx < 16384; idx += 256) {
            int e = idx >> 7, j = idx & 127;
            float v = shB1c[j];
#pragma unroll
            for (int k = 0; k < 4; ++k) v = fmaf(shEA[e * 4 + k], shW1[k * 128 + j], v);
            v = (v >= 0.f) ? v : a * v;
            __half h = __float2half_rn(v);
            shAh[e * LDAH_ + j] = h;
            shAl[e * LDAH_ + j] = __float2half_rn(v - __half2float(h));
        }
        __syncthreads();   // S2

        float acc[4][4][4] = {};
        mma_tile_3x(acc, smem_u32(shAh), smem_u32(shAl), smem_u32(shBh), smem_u32(shBl),
                    wm, wn, lane);
        stage_acc(shStage, acc, wm, wn, lane);
        __syncthreads();   // S3

        float4 bv0 = *(const float4*)&shB2c[tx * 8];
        float4 bv1 = *(const float4*)&shB2c[tx * 8 + 4];
#pragma unroll
        for (int i = 0; i < 8; ++i) {
            int r = ty * 8 + i;
            int s = sreg[i], d = dreg[i];
            const float4 cx0 = *(const float4*)&g_cx[s * HH_ + tx * 8];
            const float4 cx1 = *(const float4*)&g_cx[s * HH_ + tx * 8 + 4];
            const float* row = &shStage[r * 132 + tx * 8];
            float m0 = fmaxf(0.f, row[0] + bv0.x + cx0.x);
            float m1 = fmaxf(0.f, row[1] + bv0.y + cx0.y);
            float m2 = fmaxf(0.f, row[2] + bv0.z + cx0.z);
            float m3 = fmaxf(0.f, row[3] + bv0.w + cx0.w);
            float m4 = fmaxf(0.f, row[4] + bv1.x + cx1.x);
            float m5 = fmaxf(0.f, row[5] + bv1.y + cx1.y);
            float m6 = fmaxf(0.f, row[6] + bv1.z + cx1.z);
            float m7 = fmaxf(0.f, row[7] + bv1.w + cx1.w);
            red_add_v4(&g_agg[d * HH_ + tx * 8], m0, m1, m2, m3);
            red_add_v4(&g_agg[d * HH_ + tx * 8 + 4], m4, m5, m6, m7);
        }
        // next iter's writes (shEA/shSrc) race-free: all reads of those done pre-S2;
        // shStage reads here complete before next S2 (stage writes of t+1 come after it).
        __syncthreads();   // S4: protect shStage reads vs next stage_acc? (stage_acc of
                           // t+1 happens after S2 of t+1, which is after this point for
                           // all threads only if a sync separates; keep S4 for safety)
    }
}

// ---------------------------------------------------------------------------
// K_mlp: 256 CTAs x 32 rows. t=(1+eps)cx+agg; 2-layer MLP; store z + hi/lo.
__global__ void __launch_bounds__(256)
k_mlp(const float* __restrict__ W1, const float* __restrict__ b1,
      const float* __restrict__ a_p,
      const float* __restrict__ W2, const float* __restrict__ b2,
      const float* __restrict__ eps_p, float* __restrict__ out_z)
{
    __shared__ float shA[32 * 129];
    __shared__ float shB[32 * 128];
    int tid = threadIdx.x;
    int tx = tid & 15, ty = tid >> 4;
    int base = blockIdx.x * 32;

    float ep = 1.0f + *eps_p;
    for (int idx = tid; idx < 32 * 128; idx += 256) {
        int r = idx >> 7, k = idx & 127;
        int g = (base + r) * HH_ + k;
        shA[r * 129 + k] = ep * g_cx[g] + g_agg[g];
    }

    float acc[2][8];
#pragma unroll
    for (int i = 0; i < 2; ++i)
#pragma unroll
        for (int j = 0; j < 8; ++j) acc[i][j] = 0.f;

    for (int kc = 0; kc < HH_; kc += 32) {
        __syncthreads();
        for (int idx = tid; idx < 32 * 128; idx += 256) shB[idx] = W1[kc * 128 + idx];
        __syncthreads();
#pragma unroll 4
        for (int k = 0; k < 32; ++k) {
            float a0 = shA[(ty * 2 + 0) * 129 + kc + k];
            float a1 = shA[(ty * 2 + 1) * 129 + kc + k];
            float4 b0 = *(const float4*)&shB[k * 128 + tx * 8];
            float4 b1v = *(const float4*)&shB[k * 128 + tx * 8 + 4];
            float bfr[8] = {b0.x, b0.y, b0.z, b0.w, b1v.x, b1v.y, b1v.z, b1v.w};
#pragma unroll
            for (int j = 0; j < 8; ++j) {
                acc[0][j] = fmaf(a0, bfr[j], acc[0][j]);
                acc[1][j] = fmaf(a1, bfr[j], acc[1][j]);
            }
        }
    }

    float a = *a_p;
    __syncthreads();
#pragma unroll
    for (int i = 0; i < 2; ++i)
#pragma unroll
        for (int j = 0; j < 8; ++j) {
            float v = acc[i][j] + b1[tx * 8 + j];
            v = (v >= 0.f) ? v : a * v;
            shA[(ty * 2 + i) * 129 + tx * 8 + j] = v;
            acc[i][j] = 0.f;
        }

    for (int kc = 0; kc < HH_; kc += 32) {
        __syncthreads();
        for (int idx = tid; idx < 32 * 128; idx += 256) shB[idx] = W2[kc * 128 + idx];
        __syncthreads();
#pragma unroll 4
        for (int k = 0; k < 32; ++k) {
            float a0 = shA[(ty * 2 + 0) * 129 + kc + k];
            float a1 = shA[(ty * 2 + 1) * 129 + kc + k];
            float4 b0 = *(const float4*)&shB[k * 128 + tx * 8];
            float4 b1v = *(const float4*)&shB[k * 128 + tx * 8 + 4];
            float bfr[8] = {b0.x, b0.y, b0.z, b0.w, b1v.x, b1v.y, b1v.z, b1v.w};
#pragma unroll
            for (int j = 0; j < 8; ++j) {
                acc[0][j] = fmaf(a0, bfr[j], acc[0][j]);
                acc[1][j] = fmaf(a1, bfr[j], acc[1][j]);
            }
        }
    }

#pragma unroll
    for (int i = 0; i < 2; ++i) {
        int row = base + ty * 2 + i;
#pragma unroll
        for (int j = 0; j < 8; ++j) {
            float v = acc[i][j] + b2[tx * 8 + j];
            int g = row * HH_ + tx * 8 + j;
            g_z[g] = v;
            out_z[g] = v;
            __half h = __float2half_rn(v);
            g_zh[g] = h;
            g_zl[g] = __float2half_rn(v - __half2float(h));
        }
    }
}

// ---------------------------------------------------------------------------
// K_p: softmax(z @ pW + pb)
__global__ void k_p(const float* __restrict__ pW, const float* __restrict__ pb,
                    float* __restrict__ out_p)
{
    int tid = threadIdx.x;
    int grp = tid >> 4, lane = tid & 15;
    int node = blockIdx.x * 8 + grp;
    const float4* z4 = (const float4*)&g_z[node * HH_];
    float v = pb[lane];
#pragma unroll 8
    for (int k4 = 0; k4 < 32; ++k4) {
        float4 zz = z4[k4];
        int kb = k4 * 4;
        v += zz.x * pW[(kb + 0) * NCC_ + lane];
        v += zz.y * pW[(kb + 1) * NCC_ + lane];
        v += zz.z * pW[(kb + 2) * NCC_ + lane];
        v += zz.w * pW[(kb + 3) * NCC_ + lane];
    }
    float m = v;
#pragma unroll
    for (int off = 8; off > 0; off >>= 1)
        m = fmaxf(m, __shfl_xor_sync(0xffffffffu, m, off, 16));
    float e = expf(v - m);
    float s = e;
#pragma unroll
    for (int off = 8; off > 0; off >>= 1)
        s += __shfl_xor_sync(0xffffffffu, s, off, 16);
    out_p[node * NCC_ + lane] = e / s;
}

// ---------------------------------------------------------------------------
// K_ahat: A_hat = z z^T, HMMA fp16-split, symmetric mirror (round-4 passing).
__global__ void __launch_bounds__(256, 1)
k_ahat(float* __restrict__ outA)
{
    int bi = blockIdx.y, bj = blockIdx.x;
    if (bj < bi) return;

    extern __shared__ char smc[];
    __half* shAh = (__half*)smc;
    __half* shAl = shAh + 128 * LDAH_;
    __half* shBh = (__half*)(smc + 69632);
    __half* shBl = shBh + 128 * LDAH_;
    int tid = threadIdx.x;

    const uint4* zh4 = (const uint4*)g_zh;
    const uint4* zl4 = (const uint4*)g_zl;
    for (int idx = tid; idx < 2048; idx += 256) {
        int r = idx >> 4, kv = idx & 15;
        int ko = kv * 8;
        *(uint4*)&shAh[r * LDAH_ + ko] = zh4[(bi * 128 + r) * 16 + kv];
        *(uint4*)&shAl[r * LDAH_ + ko] = zl4[(bi * 128 + r) * 16 + kv];
        *(uint4*)&shBh[r * LDAH_ + ko] = zh4[(bj * 128 + r) * 16 + kv];
        *(uint4*)&shBl[r * LDAH_ + ko] = zl4[(bj * 128 + r) * 16 + kv];
    }
    __syncthreads();

    float acc[4][4][4] = {};
    int lane = tid & 31, w = tid >> 5;
    int wm = (w >> 2) * 64, wn = (w & 3) * 32;
    mma_tile_3x(acc, smem_u32(shAh), smem_u32(shAl), smem_u32(shBh), smem_u32(shBl),
                wm, wn, lane);

    __syncthreads();
    float* shAcc = (float*)smc;
    stage_acc(shAcc, acc, wm, wn, lane);
    __syncthreads();

    int tx = tid & 15, ty = tid >> 4;
    const size_t Ns = NN_;
#pragma unroll
    for (int i = 0; i < 8; ++i) {
        int r = ty * 8 + i;
        const float* row = &shAcc[r * 132 + tx * 8];
        float4 w0 = make_float4(row[0], row[1], row[2], row[3]);
        float4 w1 = make_float4(row[4], row[5], row[6], row[7]);
        size_t go = (size_t)(bi * 128 + r) * Ns + bj * 128 + tx * 8;
        *(float4*)&outA[go] = w0;
        *(float4*)&outA[go + 4] = w1;
    }
    if (bi != bj) {
#pragma unroll
        for (int i = 0; i < 8; ++i) {
            int u = ty * 8 + i;
            float4 w0 = make_float4(shAcc[(tx * 8 + 0) * 132 + u],
                                    shAcc[(tx * 8 + 1) * 132 + u],
                                    shAcc[(tx * 8 + 2) * 132 + u],
                                    shAcc[(tx * 8 + 3) * 132 + u]);
            float4 w1 = make_float4(shAcc[(tx * 8 + 4) * 132 + u],
                                    shAcc[(tx * 8 + 5) * 132 + u],
                                    shAcc[(tx * 8 + 6) * 132 + u],
                                    shAcc[(tx * 8 + 7) * 132 + u]);
            size_t go = (size_t)(bj * 128 + u) * Ns + bi * 128 + tx * 8;
            *(float4*)&outA[go] = w0;
            *(float4*)&outA[go + 4] = w1;
        }
    }
}

// ---------------------------------------------------------------------------
extern "C" void kernel_launch(void* const* d_in, const int* in_sizes, int n_in,
                              void* d_out, int out_size)
{
    const float* x    = (const float*)d_in[0];
    const float* ea   = (const float*)d_in[1];
    const int*   ei32 = (const int*)  d_in[2];
    const float* neW1 = (const float*)d_in[3];
    const float* neb1 = (const float*)d_in[4];
    const float* nea  = (const float*)d_in[5];
    const float* neW2 = (const float*)d_in[6];
    const float* neb2 = (const float*)d_in[7];
    const float* eeW1 = (const float*)d_in[8];
    const float* eeb1 = (const float*)d_in[9];
    const float* eea  = (const float*)d_in[10];
    const float* eeW2 = (const float*)d_in[11];
    const float* eeb2 = (const float*)d_in[12];
    const float* gW1  = (const float*)d_in[13];
    const float* gb1  = (const float*)d_in[14];
    const float* ga   = (const float*)d_in[15];
    const float* gW2  = (const float*)d_in[16];
    const float* gb2  = (const float*)d_in[17];
    const float* eps  = (const float*)d_in[18];
    const float* pW   = (const float*)d_in[19];
    const float* pb   = (const float*)d_in[20];

    float* out   = (float*)d_out;
    float* out_A = out;
    float* out_p = out + (size_t)NN_ * NN_;
    float* out_z = out_p + (size_t)NN_ * NCC_;

    const int smem_edge = 212992;
    const int smem_ahat = 139264;

    cudaFuncSetAttribute(k_edge, cudaFuncAttributeMaxDynamicSharedMemorySize, smem_edge);
    cudaFuncSetAttribute(k_ahat, cudaFuncAttributeMaxDynamicSharedMemorySize, smem_ahat);

    k_prep<<<512, 256>>>(ei32);
    k_node_enc<<<NN_ / 32, 256>>>(x, neW1, neb1, nea, neW2, neb2);
    k_split_w2<<<64, 256>>>(eeW2);
    k_edge<<<148, 256, smem_edge>>>(ea, ei32, eeW1, eeb1, eea, eeb2, EE_ / 128);
    k_mlp<<<NN_ / 32, 256>>>(gW1, gb1, ga, gW2, gb2, eps, out_z);
    k_p<<<NN_ / 8, 128>>>(pW, pb, out_p);
    k_ahat<<<dim3(NN_ / 128, NN_ / 128), 256, smem_ahat>>>(out_A);
}

// round 10
// speedup vs baseline: 1.6549x; 1.2031x over previous
#include <cuda_runtime.h>
#include <cuda_fp16.h>
#include <cstdint>

#define NN_ 8192
#define EE_ 524288
#define HH_ 128
#define IND_ 32
#define NCC_ 16

// Device scratch (static, no allocations)
__device__ __align__(16) float g_cx[NN_ * HH_];
__device__ __align__(16) float g_agg[NN_ * HH_];
__device__ __align__(16) float g_z[NN_ * HH_];
__device__ __align__(16) __half g_zh[NN_ * HH_];
__device__ __align__(16) __half g_zl[NN_ * HH_];
__device__ __align__(16) __half g_W2h[HH_ * HH_];  // eeW2^T [n][k] hi
__device__ __align__(16) __half g_W2l[HH_ * HH_];  // eeW2^T [n][k] lo
__device__ int g_is64;

// ---------------------------------------------------------------------------
__device__ __forceinline__ void red_add_v4(float* addr, float x, float y, float z, float w) {
    asm volatile("red.global.add.v4.f32 [%0], {%1,%2,%3,%4};"
                 :: "l"(addr), "f"(x), "f"(y), "f"(z), "f"(w) : "memory");
}
__device__ __forceinline__ void red_add_v2(float* addr, float x, float y) {
    asm volatile("red.global.add.v2.f32 [%0], {%1,%2};"
                 :: "l"(addr), "f"(x), "f"(y) : "memory");
}
__device__ __forceinline__ uint32_t smem_u32(const void* p) {
    return (uint32_t)__cvta_generic_to_shared(p);
}
__device__ __forceinline__ void ldmx4(uint32_t r[4], uint32_t addr) {
    asm volatile("ldmatrix.sync.aligned.m8n8.x4.shared.b16 {%0,%1,%2,%3}, [%4];"
                 : "=r"(r[0]), "=r"(r[1]), "=r"(r[2]), "=r"(r[3]) : "r"(addr));
}
__device__ __forceinline__ void mma16816(float c[4], const uint32_t a[4],
                                         uint32_t b0, uint32_t b1) {
    asm volatile("mma.sync.aligned.m16n8k16.row.col.f32.f16.f16.f32 "
                 "{%0,%1,%2,%3}, {%4,%5,%6,%7}, {%8,%9}, {%0,%1,%2,%3};"
                 : "+f"(c[0]), "+f"(c[1]), "+f"(c[2]), "+f"(c[3])
                 : "r"(a[0]), "r"(a[1]), "r"(a[2]), "r"(a[3]), "r"(b0), "r"(b1));
}

#define LDAH_ 136
// 3-term split MMA over one 128x128x128 tile; per-mt loads to cap registers.
__device__ __forceinline__ void mma_tile_3x(
    float acc[4][4][4], uint32_t sAh, uint32_t sAl, uint32_t sBh, uint32_t sBl,
    int wm, int wn, int lane)
{
    int lrow = lane & 15;
    int lcol = (lane >> 4) * 8;
#pragma unroll 1
    for (int ks = 0; ks < 8; ++ks) {
        int kk = ks * 16;
        uint32_t bh[2][4], bl[2][4];
#pragma unroll
        for (int bt = 0; bt < 2; ++bt) {
            uint32_t off = (uint32_t)(((wn + bt * 16 + lrow) * LDAH_ + kk + lcol) * 2);
            ldmx4(bh[bt], sBh + off);
            ldmx4(bl[bt], sBl + off);
        }
#pragma unroll
        for (int mt = 0; mt < 4; ++mt) {
            uint32_t ah[4], al[4];
            uint32_t off = (uint32_t)(((wm + mt * 16 + lrow) * LDAH_ + kk + lcol) * 2);
            ldmx4(ah, sAh + off);
            ldmx4(al, sAl + off);
#pragma unroll
            for (int nt = 0; nt < 4; ++nt) {
                int bt = nt >> 1, sel = nt & 1;
                mma16816(acc[mt][nt], ah, bh[bt][sel], bh[bt][sel + 2]);
                mma16816(acc[mt][nt], ah, bl[bt][sel], bl[bt][sel + 2]);
                mma16816(acc[mt][nt], al, bh[bt][sel], bh[bt][sel + 2]);
            }
        }
    }
}

__device__ __forceinline__ void stage_acc(float* shAcc, float acc[4][4][4],
                                          int wm, int wn, int lane)
{
#pragma unroll
    for (int mt = 0; mt < 4; ++mt)
#pragma unroll
        for (int nt = 0; nt < 4; ++nt) {
            int r = wm + mt * 16 + (lane >> 2);
            int c = wn + nt * 8 + (lane & 3) * 2;
            shAcc[r * 132 + c] = acc[mt][nt][0];
            shAcc[r * 132 + c + 1] = acc[mt][nt][1];
            shAcc[(r + 8) * 132 + c] = acc[mt][nt][2];
            shAcc[(r + 8) * 132 + c + 1] = acc[mt][nt][3];
        }
}

// ---------------------------------------------------------------------------
__global__ void k_prep(const int* __restrict__ ei32) {
    if (blockIdx.x == 0 && threadIdx.x == 0) {
        int all0 = 1;
        for (int i = 0; i < 64; ++i)
            if (ei32[2 * i + 1] != 0) { all0 = 0; break; }
        g_is64 = all0;
    }
    int idx = blockIdx.x * blockDim.x + threadIdx.x;
    float4* p = reinterpret_cast<float4*>(g_agg);
    int n4 = NN_ * HH_ / 4;
    for (int i = idx; i < n4; i += gridDim.x * blockDim.x)
        p[i] = make_float4(0.f, 0.f, 0.f, 0.f);
}

__global__ void k_split_w2(const float* __restrict__ W2) {
    int idx = blockIdx.x * 256 + threadIdx.x;
    int k = idx >> 7, n = idx & 127;
    float v = W2[k * 128 + n];
    __half h = __float2half_rn(v);
    g_W2h[n * 128 + k] = h;
    g_W2l[n * 128 + k] = __float2half_rn(v - __half2float(h));
}

// ---------------------------------------------------------------------------
// K_node: 256 CTAs x 32 rows
__global__ void __launch_bounds__(256)
k_node_enc(const float* __restrict__ x,
           const float* __restrict__ W1, const float* __restrict__ b1,
           const float* __restrict__ a_p,
           const float* __restrict__ W2, const float* __restrict__ b2)
{
    __shared__ float shA[32 * 129];
    __shared__ float shB[32 * 128];
    __shared__ float shX[32 * 33];
    int tid = threadIdx.x;
    int tx = tid & 15, ty = tid >> 4;
    int base = blockIdx.x * 32;

    for (int idx = tid; idx < 32 * 32; idx += 256) {
        int r = idx >> 5, k = idx & 31;
        shX[r * 33 + k] = x[(base + r) * IND_ + k];
    }
    for (int idx = tid; idx < 32 * 128; idx += 256) shB[idx] = W1[idx];
    __syncthreads();

    float acc[2][8];
#pragma unroll
    for (int i = 0; i < 2; ++i)
#pragma unroll
        for (int j = 0; j < 8; ++j) acc[i][j] = 0.f;

#pragma unroll 4
    for (int k = 0; k < 32; ++k) {
        float a0 = shX[(ty * 2 + 0) * 33 + k];
        float a1 = shX[(ty * 2 + 1) * 33 + k];
        float4 b0 = *(const float4*)&shB[k * 128 + tx * 8];
        float4 b1v = *(const float4*)&shB[k * 128 + tx * 8 + 4];
        float bfr[8] = {b0.x, b0.y, b0.z, b0.w, b1v.x, b1v.y, b1v.z, b1v.w};
#pragma unroll
        for (int j = 0; j < 8; ++j) {
            acc[0][j] = fmaf(a0, bfr[j], acc[0][j]);
            acc[1][j] = fmaf(a1, bfr[j], acc[1][j]);
        }
    }
    float a = *a_p;
#pragma unroll
    for (int i = 0; i < 2; ++i)
#pragma unroll
        for (int j = 0; j < 8; ++j) {
            float v = acc[i][j] + b1[tx * 8 + j];
            v = (v >= 0.f) ? v : a * v;
            shA[(ty * 2 + i) * 129 + tx * 8 + j] = v;
            acc[i][j] = 0.f;
        }

    for (int kc = 0; kc < HH_; kc += 32) {
        __syncthreads();
        for (int idx = tid; idx < 32 * 128; idx += 256) shB[idx] = W2[kc * 128 + idx];
        __syncthreads();
#pragma unroll 4
        for (int k = 0; k < 32; ++k) {
            float a0 = shA[(ty * 2 + 0) * 129 + kc + k];
            float a1 = shA[(ty * 2 + 1) * 129 + kc + k];
            float4 b0 = *(const float4*)&shB[k * 128 + tx * 8];
            float4 b1v = *(const float4*)&shB[k * 128 + tx * 8 + 4];
            float bfr[8] = {b0.x, b0.y, b0.z, b0.w, b1v.x, b1v.y, b1v.z, b1v.w};
#pragma unroll
            for (int j = 0; j < 8; ++j) {
                acc[0][j] = fmaf(a0, bfr[j], acc[0][j]);
                acc[1][j] = fmaf(a1, bfr[j], acc[1][j]);
            }
        }
    }
#pragma unroll
    for (int i = 0; i < 2; ++i) {
        int row = base + ty * 2 + i;
#pragma unroll
        for (int j = 0; j < 8; ++j)
            g_cx[row * HH_ + tx * 8 + j] = acc[i][j] + b2[tx * 8 + j];
    }
}

// ---------------------------------------------------------------------------
// K_edge: persistent, producer/consumer warp-specialized, double-buffered A.
// 512 threads: tid<256 = consumers (MMA+epilogue), tid>=256 = producers (h1).
// smem layout (bytes):
//   AH0=0        AH1=34816    (h1 hi, [128][136] f16, 2 bufs)
//   AL0=69632    AL1=104448   (h1 lo)
//   BH=139264    BL=174080    (W2^T hi/lo [n][k])
//   EA0=208896   EA1=210944   ([128][4] f32, 2 bufs)
//   SRC0=212992  SRC1=213504  DST0=214016  DST1=214528
//   B2C=215040   (128 f32)    total 215552
__global__ void __launch_bounds__(512, 1)
k_edge(const float* __restrict__ ea, const int* __restrict__ ei32,
       const float* __restrict__ W1, const float* __restrict__ b1,
       const float* __restrict__ a_p, const float* __restrict__ b2,
       int ntiles)
{
    extern __shared__ char smc[];
    float* shB2c = (float*)(smc + 215040);

    int tid = threadIdx.x;
    int lane = tid & 31;
    int is64 = g_is64;
    float a = *a_p;

    // one-time loads (all threads)
    {
        const uint4* wh4 = (const uint4*)g_W2h;
        const uint4* wl4 = (const uint4*)g_W2l;
        for (int idx = tid; idx < 2048; idx += 512) {
            int n = idx >> 4, ko = (idx & 15) * 8;
            *(uint4*)(smc + 139264 + (n * LDAH_ + ko) * 2) = wh4[idx];
            *(uint4*)(smc + 174080 + (n * LDAH_ + ko) * 2) = wl4[idx];
        }
        if (tid < 128) shB2c[tid] = b2[tid];
    }

    int iters = (ntiles - blockIdx.x + gridDim.x - 1) / gridDim.x;

    if (tid >= 256) {
        // ---------------- PRODUCER ----------------
        int ptid = tid - 256;
        int jp = (ptid & 63) * 2;      // column pair
        int eoff = ptid >> 6;          // 0..3
        float w1a[4], w1b[4];
#pragma unroll
        for (int k = 0; k < 4; ++k) {
            w1a[k] = W1[k * 128 + jp];
            w1b[k] = W1[k * 128 + jp + 1];
        }
        float b1a = b1[jp], b1b = b1[jp + 1];

        // fill buffer nb with tile t
        auto fill = [&](int nb, int t) {
            int e0 = t * 128;
            float* shEA = (float*)(smc + 208896 + nb * 2048);
            int* shSrc = (int*)(smc + 212992 + nb * 512);
            int* shDst = (int*)(smc + 214016 + nb * 512);
            for (int idx = ptid; idx < 512; idx += 256) shEA[idx] = ea[e0 * 4 + idx];
            if (ptid < 128) {
                if (is64) {
                    shSrc[ptid] = ei32[2 * (e0 + ptid)];
                    shDst[ptid] = ei32[2 * (EE_ + e0 + ptid)];
                } else {
                    shSrc[ptid] = ei32[e0 + ptid];
                    shDst[ptid] = ei32[EE_ + e0 + ptid];
                }
            }
            asm volatile("bar.sync 1, 256;" ::: "memory");
            char* pAh = smc + nb * 34816;
            char* pAl = smc + 69632 + nb * 34816;
#pragma unroll 4
            for (int k = 0; k < 32; ++k) {
                int e = eoff + 4 * k;
                float4 er = *(const float4*)&shEA[e * 4];
                float v0 = b1a, v1 = b1b;
                v0 = fmaf(er.x, w1a[0], v0); v1 = fmaf(er.x, w1b[0], v1);
                v0 = fmaf(er.y, w1a[1], v0); v1 = fmaf(er.y, w1b[1], v1);
                v0 = fmaf(er.z, w1a[2], v0); v1 = fmaf(er.z, w1b[2], v1);
                v0 = fmaf(er.w, w1a[3], v0); v1 = fmaf(er.w, w1b[3], v1);
                v0 = (v0 >= 0.f) ? v0 : a * v0;
                v1 = (v1 >= 0.f) ? v1 : a * v1;
                __half h0 = __float2half_rn(v0), h1 = __float2half_rn(v1);
                __half l0 = __float2half_rn(v0 - __half2float(h0));
                __half l1 = __float2half_rn(v1 - __half2float(h1));
                uint32_t hw = __half_as_ushort(h0) | ((uint32_t)__half_as_ushort(h1) << 16);
                uint32_t lw = __half_as_ushort(l0) | ((uint32_t)__half_as_ushort(l1) << 16);
                *(uint32_t*)(pAh + (e * LDAH_ + jp) * 2) = hw;
                *(uint32_t*)(pAl + (e * LDAH_ + jp) * 2) = lw;
            }
        };

        fill(0, blockIdx.x);           // prologue
        __syncthreads();
        for (int i = 0; i < iters; ++i) {
            int nt = i + 1;
            if (nt < iters) fill(nt & 1, blockIdx.x + nt * gridDim.x);
            __syncthreads();
        }
    } else {
        // ---------------- CONSUMER ----------------
        int w = tid >> 5;
        int wm = (w >> 2) * 64, wn = (w & 3) * 32;
        uint32_t sBh = smem_u32(smc + 139264);
        uint32_t sBl = smem_u32(smc + 174080);

        __syncthreads();               // matches producer prologue
        for (int i = 0; i < iters; ++i) {
            int cb = i & 1;
            uint32_t sAh = smem_u32(smc + cb * 34816);
            uint32_t sAl = smem_u32(smc + 69632 + cb * 34816);
            int* shSrc = (int*)(smc + 212992 + cb * 512);
            int* shDst = (int*)(smc + 214016 + cb * 512);

            float acc[4][4][4] = {};
            mma_tile_3x(acc, sAh, sAl, sBh, sBl, wm, wn, lane);

            // epilogue directly from fragment layout
            int r0 = lane >> 2;
            int cc = (lane & 3) * 2;
#pragma unroll
            for (int mt = 0; mt < 4; ++mt) {
                int rA = wm + mt * 16 + r0;
                int rB = rA + 8;
                int sA = shSrc[rA], dA = shDst[rA];
                int sB = shSrc[rB], dB = shDst[rB];
#pragma unroll
                for (int nt = 0; nt < 4; ++nt) {
                    int c = wn + nt * 8 + cc;
                    float2 cxA = *(const float2*)&g_cx[sA * HH_ + c];
                    float2 cxB = *(const float2*)&g_cx[sB * HH_ + c];
                    float b2a = shB2c[c], b2b = shB2c[c + 1];
                    float m0 = fmaxf(0.f, acc[mt][nt][0] + b2a + cxA.x);
                    float m1 = fmaxf(0.f, acc[mt][nt][1] + b2b + cxA.y);
                    float m2 = fmaxf(0.f, acc[mt][nt][2] + b2a + cxB.x);
                    float m3 = fmaxf(0.f, acc[mt][nt][3] + b2b + cxB.y);
                    red_add_v2(&g_agg[dA * HH_ + c], m0, m1);
                    red_add_v2(&g_agg[dB * HH_ + c], m2, m3);
                }
            }
            __syncthreads();
        }
    }
}

// ---------------------------------------------------------------------------
// K_mlp: 256 CTAs x 32 rows
__global__ void __launch_bounds__(256)
k_mlp(const float* __restrict__ W1, const float* __restrict__ b1,
      const float* __restrict__ a_p,
      const float* __restrict__ W2, const float* __restrict__ b2,
      const float* __restrict__ eps_p, float* __restrict__ out_z)
{
    __shared__ float shA[32 * 129];
    __shared__ float shB[32 * 128];
    int tid = threadIdx.x;
    int tx = tid & 15, ty = tid >> 4;
    int base = blockIdx.x * 32;

    float ep = 1.0f + *eps_p;
    for (int idx = tid; idx < 32 * 128; idx += 256) {
        int r = idx >> 7, k = idx & 127;
        int g = (base + r) * HH_ + k;
        shA[r * 129 + k] = ep * g_cx[g] + g_agg[g];
    }

    float acc[2][8];
#pragma unroll
    for (int i = 0; i < 2; ++i)
#pragma unroll
        for (int j = 0; j < 8; ++j) acc[i][j] = 0.f;

    for (int kc = 0; kc < HH_; kc += 32) {
        __syncthreads();
        for (int idx = tid; idx < 32 * 128; idx += 256) shB[idx] = W1[kc * 128 + idx];
        __syncthreads();
#pragma unroll 4
        for (int k = 0; k < 32; ++k) {
            float a0 = shA[(ty * 2 + 0) * 129 + kc + k];
            float a1 = shA[(ty * 2 + 1) * 129 + kc + k];
            float4 b0 = *(const float4*)&shB[k * 128 + tx * 8];
            float4 b1v = *(const float4*)&shB[k * 128 + tx * 8 + 4];
            float bfr[8] = {b0.x, b0.y, b0.z, b0.w, b1v.x, b1v.y, b1v.z, b1v.w};
#pragma unroll
            for (int j = 0; j < 8; ++j) {
                acc[0][j] = fmaf(a0, bfr[j], acc[0][j]);
                acc[1][j] = fmaf(a1, bfr[j], acc[1][j]);
            }
        }
    }

    float a = *a_p;
    __syncthreads();
#pragma unroll
    for (int i = 0; i < 2; ++i)
#pragma unroll
        for (int j = 0; j < 8; ++j) {
            float v = acc[i][j] + b1[tx * 8 + j];
            v = (v >= 0.f) ? v : a * v;
            shA[(ty * 2 + i) * 129 + tx * 8 + j] = v;
            acc[i][j] = 0.f;
        }

    for (int kc = 0; kc < HH_; kc += 32) {
        __syncthreads();
        for (int idx = tid; idx < 32 * 128; idx += 256) shB[idx] = W2[kc * 128 + idx];
        __syncthreads();
#pragma unroll 4
        for (int k = 0; k < 32; ++k) {
            float a0 = shA[(ty * 2 + 0) * 129 + kc + k];
            float a1 = shA[(ty * 2 + 1) * 129 + kc + k];
            float4 b0 = *(const float4*)&shB[k * 128 + tx * 8];
            float4 b1v = *(const float4*)&shB[k * 128 + tx * 8 + 4];
            float bfr[8] = {b0.x, b0.y, b0.z, b0.w, b1v.x, b1v.y, b1v.z, b1v.w};
#pragma unroll
            for (int j = 0; j < 8; ++j) {
                acc[0][j] = fmaf(a0, bfr[j], acc[0][j]);
                acc[1][j] = fmaf(a1, bfr[j], acc[1][j]);
            }
        }
    }

#pragma unroll
    for (int i = 0; i < 2; ++i) {
        int row = base + ty * 2 + i;
#pragma unroll
        for (int j = 0; j < 8; ++j) {
            float v = acc[i][j] + b2[tx * 8 + j];
            int g = row * HH_ + tx * 8 + j;
            g_z[g] = v;
            out_z[g] = v;
            __half h = __float2half_rn(v);
            g_zh[g] = h;
            g_zl[g] = __float2half_rn(v - __half2float(h));
        }
    }
}

// ---------------------------------------------------------------------------
__global__ void k_p(const float* __restrict__ pW, const float* __restrict__ pb,
                    float* __restrict__ out_p)
{
    int tid = threadIdx.x;
    int grp = tid >> 4, lane = tid & 15;
    int node = blockIdx.x * 8 + grp;
    const float4* z4 = (const float4*)&g_z[node * HH_];
    float v = pb[lane];
#pragma unroll 8
    for (int k4 = 0; k4 < 32; ++k4) {
        float4 zz = z4[k4];
        int kb = k4 * 4;
        v += zz.x * pW[(kb + 0) * NCC_ + lane];
        v += zz.y * pW[(kb + 1) * NCC_ + lane];
        v += zz.z * pW[(kb + 2) * NCC_ + lane];
        v += zz.w * pW[(kb + 3) * NCC_ + lane];
    }
    float m = v;
#pragma unroll
    for (int off = 8; off > 0; off >>= 1)
        m = fmaxf(m, __shfl_xor_sync(0xffffffffu, m, off, 16));
    float e = expf(v - m);
    float s = e;
#pragma unroll
    for (int off = 8; off > 0; off >>= 1)
        s += __shfl_xor_sync(0xffffffffu, s, off, 16);
    out_p[node * NCC_ + lane] = e / s;
}

// ---------------------------------------------------------------------------
// K_ahat: A_hat = z z^T, HMMA fp16-split, symmetric mirror
__global__ void __launch_bounds__(256, 1)
k_ahat(float* __restrict__ outA)
{
    int bi = blockIdx.y, bj = blockIdx.x;
    if (bj < bi) return;

    extern __shared__ char smc[];
    __half* shAh = (__half*)smc;
    __half* shAl = shAh + 128 * LDAH_;
    __half* shBh = (__half*)(smc + 69632);
    __half* shBl = shBh + 128 * LDAH_;
    int tid = threadIdx.x;

    const uint4* zh4 = (const uint4*)g_zh;
    const uint4* zl4 = (const uint4*)g_zl;
    for (int idx = tid; idx < 2048; idx += 256) {
        int r = idx >> 4, kv = idx & 15;
        int ko = kv * 8;
        *(uint4*)&shAh[r * LDAH_ + ko] = zh4[(bi * 128 + r) * 16 + kv];
        *(uint4*)&shAl[r * LDAH_ + ko] = zl4[(bi * 128 + r) * 16 + kv];
        *(uint4*)&shBh[r * LDAH_ + ko] = zh4[(bj * 128 + r) * 16 + kv];
        *(uint4*)&shBl[r * LDAH_ + ko] = zl4[(bj * 128 + r) * 16 + kv];
    }
    __syncthreads();

    float acc[4][4][4] = {};
    int lane = tid & 31, w = tid >> 5;
    int wm = (w >> 2) * 64, wn = (w & 3) * 32;
    mma_tile_3x(acc, smem_u32(shAh), smem_u32(shAl), smem_u32(shBh), smem_u32(shBl),
                wm, wn, lane);

    __syncthreads();
    float* shAcc = (float*)smc;
    stage_acc(shAcc, acc, wm, wn, lane);
    __syncthreads();

    int tx = tid & 15, ty = tid >> 4;
    const size_t Ns = NN_;
#pragma unroll
    for (int i = 0; i < 8; ++i) {
        int r = ty * 8 + i;
        const float* row = &shAcc[r * 132 + tx * 8];
        float4 w0 = make_float4(row[0], row[1], row[2], row[3]);
        float4 w1 = make_float4(row[4], row[5], row[6], row[7]);
        size_t go = (size_t)(bi * 128 + r) * Ns + bj * 128 + tx * 8;
        *(float4*)&outA[go] = w0;
        *(float4*)&outA[go + 4] = w1;
    }
    if (bi != bj) {
#pragma unroll
        for (int i = 0; i < 8; ++i) {
            int u = ty * 8 + i;
            float4 w0 = make_float4(shAcc[(tx * 8 + 0) * 132 + u],
                                    shAcc[(tx * 8 + 1) * 132 + u],
                                    shAcc[(tx * 8 + 2) * 132 + u],
                                    shAcc[(tx * 8 + 3) * 132 + u]);
            float4 w1 = make_float4(shAcc[(tx * 8 + 4) * 132 + u],
                                    shAcc[(tx * 8 + 5) * 132 + u],
                                    shAcc[(tx * 8 + 6) * 132 + u],
                                    shAcc[(tx * 8 + 7) * 132 + u]);
            size_t go = (size_t)(bj * 128 + u) * Ns + bi * 128 + tx * 8;
            *(float4*)&outA[go] = w0;
            *(float4*)&outA[go + 4] = w1;
        }
    }
}

// ---------------------------------------------------------------------------
extern "C" void kernel_launch(void* const* d_in, const int* in_sizes, int n_in,
                              void* d_out, int out_size)
{
    const float* x    = (const float*)d_in[0];
    const float* ea   = (const float*)d_in[1];
    const int*   ei32 = (const int*)  d_in[2];
    const float* neW1 = (const float*)d_in[3];
    const float* neb1 = (const float*)d_in[4];
    const float* nea  = (const float*)d_in[5];
    const float* neW2 = (const float*)d_in[6];
    const float* neb2 = (const float*)d_in[7];
    const float* eeW1 = (const float*)d_in[8];
    const float* eeb1 = (const float*)d_in[9];
    const float* eea  = (const float*)d_in[10];
    const float* eeW2 = (const float*)d_in[11];
    const float* eeb2 = (const float*)d_in[12];
    const float* gW1  = (const float*)d_in[13];
    const float* gb1  = (const float*)d_in[14];
    const float* ga   = (const float*)d_in[15];
    const float* gW2  = (const float*)d_in[16];
    const float* gb2  = (const float*)d_in[17];
    const float* eps  = (const float*)d_in[18];
    const float* pW   = (const float*)d_in[19];
    const float* pb   = (const float*)d_in[20];

    float* out   = (float*)d_out;
    float* out_A = out;
    float* out_p = out + (size_t)NN_ * NN_;
    float* out_z = out_p + (size_t)NN_ * NCC_;

    const int smem_edge = 215552;
    const int smem_ahat = 139264;

    cudaFuncSetAttribute(k_edge, cudaFuncAttributeMaxDynamicSharedMemorySize, smem_edge);
    cudaFuncSetAttribute(k_ahat, cudaFuncAttributeMaxDynamicSharedMemorySize, smem_ahat);

    k_prep<<<512, 256>>>(ei32);
    k_node_enc<<<NN_ / 32, 256>>>(x, neW1, neb1, nea, neW2, neb2);
    k_split_w2<<<64, 256>>>(eeW2);
    k_edge<<<148, 512, smem_edge>>>(ea, ei32, eeW1, eeb1, eea, eeb2, EE_ / 128);
    k_mlp<<<NN_ / 32, 256>>>(gW1, gb1, ga, gW2, gb2, eps, out_z);
    k_p<<<NN_ / 8, 128>>>(pW, pb, out_p);
    k_ahat<<<dim3(NN_ / 128, NN_ / 128), 256, smem_ahat>>>(out_A);
}